// round 11
// baseline (speedup 1.0000x reference)
#include <cuda_runtime.h>
#include <cuda_fp16.h>
#include <cstdint>

#define BB  8
#define N0  8192
#define NP  2048
#define CPf 512
#define CSf 256
#define C1f 256
#define C2f 256
#define KW  768   // CP+CS

// smem row: 64 fp16 (128B) | pad 16B
#define PITCH 144
#define O_A0  0                  // A stage: 64 rows  (9216 B)
#define O_A1  9216
#define O_B0  18432              // B stage: 128 rows (18432 B)
#define O_B1  36864
#define SM_BYTES 55296
// epilogue overlays (after mainloop)
#define O_SBUF 0                 // 32 x 68 floats = 8704 B
#define O_SID  8704              // 192 int
#define O_SWT  9472              // 192 float
#define O_CHS  10240             // 128 float
#define O_CHQ  10752             // 128 float

// ---------------- scratch (device globals) ----------------
__device__ int   g_idx[BB*N0*3];
__device__ float g_wt [BB*N0*3];
__device__ float g_Gt [BB*NP*C1f];
__device__ float g_y1 [BB*C1f*N0];
__device__ float g_z  [BB*C2f*N0];
__device__ float g_p1 [C1f*1024], g_p2[C1f*1024];
__device__ float g_sc1[C1f], g_bi1[C1f], g_sc2[C2f], g_bi2[C2f];
// pre-converted weights (fp16, row-major [o][k])
__device__ __align__(16) __half g_W1_h[C1f*KW];
__device__ __align__(16) __half g_W2_h[C2f*C1f];

// ---------------- PTX wrappers (baseline ISA, compute_103-safe) ----------------
__device__ __forceinline__ uint32_t smem_u32(const void* p) {
    uint32_t a;
    asm("{ .reg .u64 t; cvta.to.shared.u64 t, %1; cvt.u32.u64 %0, t; }" : "=r"(a) : "l"(p));
    return a;
}
__device__ __forceinline__ void ldm4(uint32_t* r, uint32_t addr) {
    asm volatile("ldmatrix.sync.aligned.m8n8.x4.shared.b16 {%0,%1,%2,%3}, [%4];"
        : "=r"(r[0]), "=r"(r[1]), "=r"(r[2]), "=r"(r[3]) : "r"(addr));
}
__device__ __forceinline__ void mma_f16(float* d, const uint32_t* a, const uint32_t* b) {
    asm volatile("mma.sync.aligned.m16n8k16.row.col.f32.f16.f16.f32 "
        "{%0,%1,%2,%3}, {%4,%5,%6,%7}, {%8,%9}, {%0,%1,%2,%3};"
        : "+f"(d[0]), "+f"(d[1]), "+f"(d[2]), "+f"(d[3])
        : "r"(a[0]), "r"(a[1]), "r"(a[2]), "r"(a[3]), "r"(b[0]), "r"(b[1]));
}
__device__ __forceinline__ uint32_t pack_h2(float a, float b) {
    __half2 p = __floats2half2_rn(a, b);
    return *(uint32_t*)&p;
}
__device__ __forceinline__ void cpa16(uint32_t dst, const void* src) {
    asm volatile("cp.async.cg.shared.global [%0], [%1], 16;" :: "r"(dst), "l"(src) : "memory");
}
#define CP_COMMIT() asm volatile("cp.async.commit_group;" ::: "memory")
#define CP_WAIT(n)  asm volatile("cp.async.wait_group %0;" :: "n"(n) : "memory")

// ---------------- kNN ----------------
__global__ void knn_kernel(const float* __restrict__ xyz,
                           const float* __restrict__ xyzp) {
    __shared__ float4 sp[NP];
    int b = blockIdx.y;
    const float* p = xyzp + (size_t)b*3*NP;
    for (int j = threadIdx.x; j < NP; j += blockDim.x) {
        float X = p[j], Y = p[NP + j], Z = p[2*NP + j];
        sp[j] = make_float4(X, Y, Z, X*X + Y*Y + Z*Z);
    }
    __syncthreads();
    int n = blockIdx.x*blockDim.x + threadIdx.x;
    const float* q = xyz + (size_t)b*3*N0;
    float qx = q[n], qy = q[N0 + n], qz = q[2*N0 + n];
    float q2 = qx*qx + qy*qy + qz*qz;
    float d0 = 1e30f, d1 = 1e30f, d2 = 1e30f;
    int   i0 = 0, i1 = 0, i2 = 0;
#pragma unroll 4
    for (int j = 0; j < NP; ++j) {
        float4 v = sp[j];
        float dot = qx*v.x + qy*v.y + qz*v.z;
        float d = (q2 + v.w) - 2.0f*dot;
        if (d < d2) {
            if (d < d1) {
                d2 = d1; i2 = i1;
                if (d < d0) { d1 = d0; i1 = i0; d0 = d; i0 = j; }
                else        { d1 = d;  i1 = j; }
            } else { d2 = d; i2 = j; }
        }
    }
    float e0 = 1.0f/(fmaxf(d0, 1e-10f) + 1e-8f);
    float e1 = 1.0f/(fmaxf(d1, 1e-10f) + 1e-8f);
    float e2 = 1.0f/(fmaxf(d2, 1e-10f) + 1e-8f);
    float inv = 1.0f/(e0 + e1 + e2);
    size_t base = ((size_t)b*N0 + n)*3;
    g_idx[base]   = i0; g_idx[base+1] = i1; g_idx[base+2] = i2;
    g_wt [base]   = e0*inv; g_wt[base+1] = e1*inv; g_wt[base+2] = e2*inv;
}

// ---------------- weight convert (elementwise, fp16) ----------------
__global__ void wconv_kernel(const float* __restrict__ w,
                             __half* __restrict__ hi, int npairs) {
    int i = blockIdx.x*blockDim.x + threadIdx.x;
    if (i >= npairs) return;
    ((uint32_t*)hi)[i] = pack_h2(w[2*i], w[2*i + 1]);
}

// ===================== fp16 mma.sync GEMM core =====================
// 256 threads, 8 warps (2 n x 4 o), CTA tile 64n x 128o, K chunk 64, 2 CTAs/SM.
// A: fp32 LDG + in-loop fp16 convert, double-buffered smem.
// B: fp16 pre-converted, 2-stage cp.async. One __syncthreads per chunk.

__device__ __forceinline__ void issue_B(uint32_t dstbase,
    const __half* __restrict__ Wh, int ldw, int ob, int k0, int rsB, int qB)
{
    const __half* src = Wh + (size_t)(ob + rsB)*ldw + k0 + qB*32;
    uint32_t dst = dstbase + rsB*PITCH + qB*64;
    cpa16(dst,      src);
    cpa16(dst + 16, src + 8);
    cpa16(dst + 32, src + 16);
    cpa16(dst + 48, src + 24);
}

template<bool BN>
__device__ __forceinline__ void conv_storeA(char* dststage, const float* ax,
                                            int kA, int rsA, int qA) {
    float x[16];
#pragma unroll
    for (int j = 0; j < 16; j++) x[j] = ax[j];
    if (BN) {
#pragma unroll
        for (int j = 0; j < 16; j++) {
            float v = fmaf(x[j], g_sc1[kA + j], g_bi1[kA + j]);
            x[j] = (v >= 0.f) ? v : 0.01f*v;
        }
    }
    char* arow = dststage + rsA*PITCH + qA*32;
    *(uint4*)arow = make_uint4(pack_h2(x[0], x[1]),  pack_h2(x[2], x[3]),
                               pack_h2(x[4], x[5]),  pack_h2(x[6], x[7]));
    *(uint4*)(arow + 16) = make_uint4(pack_h2(x[8], x[9]),   pack_h2(x[10], x[11]),
                                      pack_h2(x[12], x[13]), pack_h2(x[14], x[15]));
}

template<bool BN>
__device__ __forceinline__ void gemm_core(char* sm, uint32_t sb,
    const float* __restrict__ A, int ldn, int nb, int kA0,
    const __half* __restrict__ Wh, int ldw, int ob, int kW0,
    int nk64, float acc[2][4][4])
{
    int t = threadIdx.x, lane = t & 31, wid = t >> 5;
    int wn = wid & 1, wo = wid >> 1;
    int rsA = t & 63,  qA = t >> 6;     // A staging: 4 k-groups of 16
    int rsB = t & 127, qB = t >> 7;     // B staging: 2 k-groups of 32
    uint32_t aOff = (uint32_t)((wn*32 + (lane & 15))*PITCH + ((lane >> 4) & 1)*16);
    uint32_t bOff = (uint32_t)((wo*32 + (lane & 7) + ((lane >> 4) & 1)*8)*PITCH
                               + ((lane >> 3) & 1)*16);
    float ax[16];
    // ---- prologue: B(0) cp.async; A(0) LDG+convert into stage0; A(1) LDG ----
    issue_B(sb + O_B0, Wh, ldw, ob, kW0, rsB, qB);
    CP_COMMIT();
    {
        const float* ap = A + (size_t)(kA0 + qA*16)*ldn + nb + rsA;
#pragma unroll
        for (int j = 0; j < 16; j++) ax[j] = ap[(size_t)j*ldn];
    }
    conv_storeA<BN>(sm + O_A0, ax, qA*16, rsA, qA);
    if (nk64 > 1) {
        const float* ap = A + (size_t)(kA0 + 64 + qA*16)*ldn + nb + rsA;
#pragma unroll
        for (int j = 0; j < 16; j++) ax[j] = ap[(size_t)j*ldn];
    }
    for (int it = 0; it < nk64; it++) {
        CP_WAIT(0);              // B(it) landed
        __syncthreads();         // A(it) STS visible; stages (it+1)&1 free
        if (it + 1 < nk64) {
            issue_B(sb + (((it + 1) & 1) ? O_B1 : O_B0), Wh, ldw, ob,
                    kW0 + (it + 1)*64, rsB, qB);
            CP_COMMIT();
        }
        // ---- compute chunk it: 8 independent MMAs per k16 step ----
        uint32_t aAddr = sb + ((it & 1) ? O_A1 : O_A0) + aOff;
        uint32_t bAddr = sb + ((it & 1) ? O_B1 : O_B0) + bOff;
#pragma unroll
        for (int s16 = 0; s16 < 4; s16++) {
            uint32_t Ah[2][4], Bh[2][4];
#pragma unroll
            for (int mt = 0; mt < 2; mt++)
                ldm4(Ah[mt], aAddr + mt*16*PITCH + s16*32);
#pragma unroll
            for (int np = 0; np < 2; np++)
                ldm4(Bh[np], bAddr + np*16*PITCH + s16*32);
#pragma unroll
            for (int mt = 0; mt < 2; mt++)
#pragma unroll
            for (int nt = 0; nt < 4; nt++)
                mma_f16(acc[mt][nt], Ah[mt], &Bh[nt >> 1][(nt & 1)*2]);
        }
        // ---- convert A(it+1) into other stage; LDG A(it+2) (overlap MMA drain) ----
        if (it + 1 < nk64) {
            conv_storeA<BN>(sm + (((it + 1) & 1) ? O_A1 : O_A0), ax,
                            (it + 1)*64 + qA*16, rsA, qA);
            if (it + 2 < nk64) {
                const float* ap = A + (size_t)(kA0 + (it + 2)*64 + qA*16)*ldn + nb + rsA;
#pragma unroll
                for (int j = 0; j < 16; j++) ax[j] = ap[(size_t)j*ldn];
            }
        }
    }
    __syncthreads();
}

// dump one 32-o strip of accumulators into sbuf[o_local][n] (n = 64, stride 68)
__device__ __forceinline__ void dump_strip(float* sbuf, int s, float acc[2][4][4]) {
    int t = threadIdx.x, lane = t & 31, wid = t >> 5;
    int wn = wid & 1, wo = wid >> 1;
    if (wo != s) return;
    int g = lane >> 2, c2 = (lane & 3)*2;
#pragma unroll
    for (int mt = 0; mt < 2; mt++)
#pragma unroll
    for (int nt = 0; nt < 4; nt++) {
        int nl = wn*32 + mt*16 + g;
        int ol = nt*8 + c2;
        sbuf[ol*68 + nl]         = acc[mt][nt][0];
        sbuf[(ol+1)*68 + nl]     = acc[mt][nt][1];
        sbuf[ol*68 + nl + 8]     = acc[mt][nt][2];
        sbuf[(ol+1)*68 + nl + 8] = acc[mt][nt][3];
    }
}

// ---------- GEMM 1a: Gt[b][n][o] = W1[:, :512] @ feat ----------
__global__ __launch_bounds__(256, 2)
void gemm1a_kernel(const float* __restrict__ feat) {
    extern __shared__ __align__(16) char sm[];
    uint32_t sb = smem_u32(sm);
    int b = blockIdx.z, nb = blockIdx.x*64, ob = blockIdx.y*128;
    int t = threadIdx.x;
    float acc[2][4][4] = {};
    gemm_core<false>(sm, sb, feat + (size_t)b*CPf*NP, NP, nb, 0,
                     g_W1_h, KW, ob, 0, CPf/64, acc);
    float* sbuf = (float*)(sm + O_SBUF);
    int n = t & 63, oq = t >> 6;
    for (int s = 0; s < 4; s++) {
        __syncthreads();
        dump_strip(sbuf, s, acc);
        __syncthreads();
        float f[8];
#pragma unroll
        for (int j = 0; j < 8; j++) f[j] = sbuf[(oq*8 + j)*68 + n];
        float* dst = &g_Gt[((size_t)b*NP + nb + n)*C1f + ob + s*32 + oq*8];
        *(float4*)dst       = make_float4(f[0], f[1], f[2], f[3]);
        *(float4*)(dst + 4) = make_float4(f[4], f[5], f[6], f[7]);
    }
}

// shared epilogue: optional gather, transpose writeout [o][n], BN-stat partials
__device__ __forceinline__ void epi_write(char* sm, float acc[2][4][4],
                                          float* __restrict__ Y, int nb, int ob,
                                          int b, bool gather) {
    int t = threadIdx.x;
    float* sbuf = (float*)(sm + O_SBUF);
    int*   sid  = (int*)(sm + O_SID);
    float* swt  = (float*)(sm + O_SWT);
    float* chs  = (float*)(sm + O_CHS);
    float* chq  = (float*)(sm + O_CHQ);
    if (gather) {
        if (t < 192) {
            size_t base = ((size_t)b*N0 + nb)*3 + t;
            sid[t] = g_idx[base]; swt[t] = g_wt[base];
        }
    }
    const float* Gt = g_Gt + (size_t)b*NP*C1f;
    for (int s = 0; s < 4; s++) {
        __syncthreads();
        dump_strip(sbuf, s, acc);
        __syncthreads();
        if (gather) {
            int n = t & 63, oq = t >> 6;
            float v[8];
#pragma unroll
            for (int j = 0; j < 8; j++) v[j] = sbuf[(oq*8 + j)*68 + n];
#pragma unroll
            for (int k = 0; k < 3; k++) {
                int   id = sid[n*3 + k];
                float wk = swt[n*3 + k];
                const float* gp = &Gt[(size_t)id*C1f + ob + s*32 + oq*8];
                float4 g0 = *(const float4*)gp;
                float4 g1 = *(const float4*)(gp + 4);
                v[0] = fmaf(wk, g0.x, v[0]); v[1] = fmaf(wk, g0.y, v[1]);
                v[2] = fmaf(wk, g0.z, v[2]); v[3] = fmaf(wk, g0.w, v[3]);
                v[4] = fmaf(wk, g1.x, v[4]); v[5] = fmaf(wk, g1.y, v[5]);
                v[6] = fmaf(wk, g1.z, v[6]); v[7] = fmaf(wk, g1.w, v[7]);
            }
#pragma unroll
            for (int j = 0; j < 8; j++) sbuf[(oq*8 + j)*68 + n] = v[j];
            __syncthreads();
        }
        {
            int ol = t >> 3, seg = t & 7, n = seg*8;
            const float* srow = &sbuf[ol*68 + n];
            float4 x0 = *(const float4*)srow;
            float4 x1 = *(const float4*)(srow + 4);
            float s1 = x0.x + x0.y + x0.z + x0.w + x1.x + x1.y + x1.z + x1.w;
            float s2 = 0.f;
            s2 = fmaf(x0.x, x0.x, s2); s2 = fmaf(x0.y, x0.y, s2);
            s2 = fmaf(x0.z, x0.z, s2); s2 = fmaf(x0.w, x0.w, s2);
            s2 = fmaf(x1.x, x1.x, s2); s2 = fmaf(x1.y, x1.y, s2);
            s2 = fmaf(x1.z, x1.z, s2); s2 = fmaf(x1.w, x1.w, s2);
            float* dst = &Y[(size_t)(ob + s*32 + ol)*N0 + nb + n];
            *(float4*)dst       = x0;
            *(float4*)(dst + 4) = x1;
#pragma unroll
            for (int off = 4; off; off >>= 1) {
                s1 += __shfl_down_sync(0xffffffffu, s1, off, 8);
                s2 += __shfl_down_sync(0xffffffffu, s2, off, 8);
            }
            if (seg == 0) { chs[s*32 + ol] = s1; chq[s*32 + ol] = s2; }
        }
    }
    __syncthreads();
    if (t < 128) {
        int pidx = blockIdx.x + (int)gridDim.x*blockIdx.z;   // < 1024
        g_p1[(size_t)(ob + t)*1024 + pidx] = chs[t];
        g_p2[(size_t)(ob + t)*1024 + pidx] = chq[t];
    }
}

// ---- GEMM 1b: y1 = W1[:, 512:] @ skip + interp(Gt); fused stats ----
__global__ __launch_bounds__(256, 2)
void gemm1b_kernel(const float* __restrict__ skip) {
    extern __shared__ __align__(16) char sm[];
    uint32_t sb = smem_u32(sm);
    int b = blockIdx.z, nb = blockIdx.x*64, ob = blockIdx.y*128;
    float acc[2][4][4] = {};
    gemm_core<false>(sm, sb, skip + (size_t)b*CSf*N0, N0, nb, 0,
                     g_W1_h, KW, ob, CPf, CSf/64, acc);
    epi_write(sm, acc, g_y1 + (size_t)b*C1f*N0, nb, ob, b, true);
}

// ---- GEMM 2: z = W2 @ lrelu(BN1(y1)); BN on A-stage; fused stats ----
__global__ __launch_bounds__(256, 2)
void gemm2_kernel() {
    extern __shared__ __align__(16) char sm[];
    uint32_t sb = smem_u32(sm);
    int b = blockIdx.z, nb = blockIdx.x*64, ob = blockIdx.y*128;
    float acc[2][4][4] = {};
    gemm_core<true>(sm, sb, g_y1 + (size_t)b*C1f*N0, N0, nb, 0,
                    g_W2_h, C1f, ob, 0, C1f/64, acc);
    epi_write(sm, acc, g_z + (size_t)b*C2f*N0, nb, ob, b, false);
}

// ---------------- stats reduce (1024 partials per channel) ----------------
__global__ void stats_reduce(const float* __restrict__ gain,
                             const float* __restrict__ beta, int layer) {
    int o = blockIdx.x, t = threadIdx.x;   // 128 threads
    const float* p1 = &g_p1[(size_t)o*1024];
    const float* p2 = &g_p2[(size_t)o*1024];
    float a = 0.f, c = 0.f;
#pragma unroll
    for (int j = 0; j < 8; j++) { a += p1[t + 128*j]; c += p2[t + 128*j]; }
    __shared__ float r1[128], r2[128];
    r1[t] = a; r2[t] = c; __syncthreads();
    for (int h = 64; h > 0; h >>= 1) {
        if (t < h) { r1[t] += r1[t+h]; r2[t] += r2[t+h]; }
        __syncthreads();
    }
    if (t == 0) {
        const float invN = 1.0f/((float)BB*N0);
        float m   = r1[0]*invN;
        float var = r2[0]*invN - m*m;
        float sc  = gain[o] * (1.0f/sqrtf(var + 1e-3f));
        if (layer) { g_sc2[o] = sc; g_bi2[o] = beta[o] - m*sc; }
        else       { g_sc1[o] = sc; g_bi1[o] = beta[o] - m*sc; }
    }
}

// ---------------- output: lrelu(BN2(z)) ----------------
__global__ void out_kernel(float* __restrict__ out) {
    size_t i = (size_t)blockIdx.x*blockDim.x + threadIdx.x;
    const size_t total4 = (size_t)BB*C2f*N0/4;
    if (i >= total4) return;
    int ch = (int)((i/(N0/4)) % C2f);
    float sc = g_sc2[ch], bi = g_bi2[ch];
    float4 v = *((const float4*)g_z + i);
    v.x = fmaf(v.x, sc, bi); v.x = (v.x >= 0.f) ? v.x : 0.01f*v.x;
    v.y = fmaf(v.y, sc, bi); v.y = (v.y >= 0.f) ? v.y : 0.01f*v.y;
    v.z = fmaf(v.z, sc, bi); v.z = (v.z >= 0.f) ? v.z : 0.01f*v.z;
    v.w = fmaf(v.w, sc, bi); v.w = (v.w >= 0.f) ? v.w : 0.01f*v.w;
    *((float4*)out + i) = v;
}

// ---------------- launch ----------------
extern "C" void kernel_launch(void* const* d_in, const int* in_sizes, int n_in,
                              void* d_out, int out_size) {
    const float* xyz   = (const float*)d_in[0];
    const float* skip  = (const float*)d_in[1];
    const float* xyzp  = (const float*)d_in[2];
    const float* featp = (const float*)d_in[3];
    const float* W1    = (const float*)d_in[4];
    const float* g1    = (const float*)d_in[5];
    const float* b1    = (const float*)d_in[6];
    const float* W2    = (const float*)d_in[7];
    const float* g2    = (const float*)d_in[8];
    const float* b2    = (const float*)d_in[9];
    float* out = (float*)d_out;

    static int s_attr = 0;
    if (!s_attr) {
        cudaFuncSetAttribute(gemm1a_kernel, cudaFuncAttributeMaxDynamicSharedMemorySize, SM_BYTES);
        cudaFuncSetAttribute(gemm1b_kernel, cudaFuncAttributeMaxDynamicSharedMemorySize, SM_BYTES);
        cudaFuncSetAttribute(gemm2_kernel,  cudaFuncAttributeMaxDynamicSharedMemorySize, SM_BYTES);
        s_attr = 1;
    }

    __half *w1_h, *w2_h;
    cudaGetSymbolAddress((void**)&w1_h, g_W1_h);
    cudaGetSymbolAddress((void**)&w2_h, g_W2_h);

    const size_t xyz_elems = (size_t)BB*3*N0;
    const size_t nf_elems  = (size_t)BB*C2f*N0;
    size_t off = 0;
    if ((size_t)out_size >= xyz_elems + nf_elems) {
        cudaMemcpyAsync(out, xyz, xyz_elems*sizeof(float), cudaMemcpyDeviceToDevice);
        off = xyz_elems;
    }

    knn_kernel   <<<dim3(N0/256, BB), 256>>>(xyz, xyzp);
    wconv_kernel <<<(C1f*KW/2 + 255)/256,  256>>>(W1, w1_h, C1f*KW/2);
    wconv_kernel <<<(C2f*C1f/2 + 255)/256, 256>>>(W2, w2_h, C2f*C1f/2);
    gemm1a_kernel<<<dim3(NP/64, C1f/128, BB), 256, SM_BYTES>>>(featp);
    gemm1b_kernel<<<dim3(N0/64, C1f/128, BB), 256, SM_BYTES>>>(skip);
    stats_reduce <<<C1f, 128>>>(g1, b1, 0);
    gemm2_kernel <<<dim3(N0/64, C2f/128, BB), 256, SM_BYTES>>>();
    stats_reduce <<<C2f, 128>>>(g2, b2, 1);
    out_kernel   <<<(unsigned)((nf_elems/4 + 255)/256), 256>>>(out + off);
}

// round 12
// speedup vs baseline: 1.0492x; 1.0492x over previous
#include <cuda_runtime.h>
#include <cuda_fp16.h>
#include <cstdint>

#define BB  8
#define N0  8192
#define NP  2048
#define CPf 512
#define CSf 256
#define C1f 256
#define C2f 256
#define KW  768   // CP+CS

#define PITCH_A 144              // 64 fp16 + 16B pad
#define EPI_BYTES 36864
// epilogue overlay offsets (relative to A-region base = B panel size)
#define O_SBUF 0                 // 32 x 132 floats = 16896
#define O_SID  16896             // 384 int
#define O_SWT  18432             // 384 float
#define O_CHS  19968             // 128 float
#define O_CHQ  20480             // 128 float

// ---------------- scratch (device globals) ----------------
__device__ int   g_idx[BB*N0*3];
__device__ float g_wt [BB*N0*3];
__device__ float g_Gt [BB*NP*C1f];
__device__ float g_y1 [BB*C1f*N0];
__device__ float g_z  [BB*C2f*N0];
__device__ float g_p1 [C1f*512], g_p2[C1f*512];
__device__ float g_sc1[C1f], g_bi1[C1f], g_sc2[C2f], g_bi2[C2f];
__device__ __align__(16) __half g_W1_h[C1f*KW];
__device__ __align__(16) __half g_W2_h[C2f*C1f];

// ---------------- PTX wrappers ----------------
__device__ __forceinline__ uint32_t smem_u32(const void* p) {
    uint32_t a;
    asm("{ .reg .u64 t; cvta.to.shared.u64 t, %1; cvt.u32.u64 %0, t; }" : "=r"(a) : "l"(p));
    return a;
}
__device__ __forceinline__ void ldm4(uint32_t* r, uint32_t addr) {
    asm volatile("ldmatrix.sync.aligned.m8n8.x4.shared.b16 {%0,%1,%2,%3}, [%4];"
        : "=r"(r[0]), "=r"(r[1]), "=r"(r[2]), "=r"(r[3]) : "r"(addr));
}
__device__ __forceinline__ void mma_f16(float* d, const uint32_t* a, const uint32_t* b) {
    asm volatile("mma.sync.aligned.m16n8k16.row.col.f32.f16.f16.f32 "
        "{%0,%1,%2,%3}, {%4,%5,%6,%7}, {%8,%9}, {%0,%1,%2,%3};"
        : "+f"(d[0]), "+f"(d[1]), "+f"(d[2]), "+f"(d[3])
        : "r"(a[0]), "r"(a[1]), "r"(a[2]), "r"(a[3]), "r"(b[0]), "r"(b[1]));
}
__device__ __forceinline__ uint32_t pack_h2(float a, float b) {
    __half2 p = __floats2half2_rn(a, b);
    return *(uint32_t*)&p;
}
__device__ __forceinline__ void cpa16(uint32_t dst, const void* src) {
    asm volatile("cp.async.cg.shared.global [%0], [%1], 16;" :: "r"(dst), "l"(src) : "memory");
}
#define CP_COMMIT() asm volatile("cp.async.commit_group;" ::: "memory")
#define CP_WAIT(n)  asm volatile("cp.async.wait_group %0;" :: "n"(n) : "memory")
#define GBAR(id)    asm volatile("bar.sync %0, 128;" :: "r"(id) : "memory")

// ---------------- kNN ----------------
__global__ void knn_kernel(const float* __restrict__ xyz,
                           const float* __restrict__ xyzp) {
    __shared__ float4 sp[NP];
    int b = blockIdx.y;
    const float* p = xyzp + (size_t)b*3*NP;
    for (int j = threadIdx.x; j < NP; j += blockDim.x) {
        float X = p[j], Y = p[NP + j], Z = p[2*NP + j];
        sp[j] = make_float4(X, Y, Z, X*X + Y*Y + Z*Z);
    }
    __syncthreads();
    int n = blockIdx.x*blockDim.x + threadIdx.x;
    const float* q = xyz + (size_t)b*3*N0;
    float qx = q[n], qy = q[N0 + n], qz = q[2*N0 + n];
    float q2 = qx*qx + qy*qy + qz*qz;
    float d0 = 1e30f, d1 = 1e30f, d2 = 1e30f;
    int   i0 = 0, i1 = 0, i2 = 0;
#pragma unroll 4
    for (int j = 0; j < NP; ++j) {
        float4 v = sp[j];
        float dot = qx*v.x + qy*v.y + qz*v.z;
        float d = (q2 + v.w) - 2.0f*dot;
        if (d < d2) {
            if (d < d1) {
                d2 = d1; i2 = i1;
                if (d < d0) { d1 = d0; i1 = i0; d0 = d; i0 = j; }
                else        { d1 = d;  i1 = j; }
            } else { d2 = d; i2 = j; }
        }
    }
    float e0 = 1.0f/(fmaxf(d0, 1e-10f) + 1e-8f);
    float e1 = 1.0f/(fmaxf(d1, 1e-10f) + 1e-8f);
    float e2 = 1.0f/(fmaxf(d2, 1e-10f) + 1e-8f);
    float inv = 1.0f/(e0 + e1 + e2);
    size_t base = ((size_t)b*N0 + n)*3;
    g_idx[base]   = i0; g_idx[base+1] = i1; g_idx[base+2] = i2;
    g_wt [base]   = e0*inv; g_wt[base+1] = e1*inv; g_wt[base+2] = e2*inv;
}

// ---------------- weight convert ----------------
__global__ void wconv_kernel(const float* __restrict__ w,
                             __half* __restrict__ hi, int npairs) {
    int i = blockIdx.x*blockDim.x + threadIdx.x;
    if (i >= npairs) return;
    ((uint32_t*)hi)[i] = pack_h2(w[2*i], w[2*i + 1]);
}

// ===================== fp16 mma.sync GEMM core =====================
// 512 threads, 16 warps = 4 groups x 4 warps. Group g owns n-rows [g*32, g*32+32),
// warp w in group owns o-cols [w*32, w*32+32). B panel (128o x KFULL) staged once.
// A double-buffered per group; one named barrier (4 warps) per 64-K chunk.

template<bool BN>
__device__ __forceinline__ void conv_storeA(char* dststage, const float* ax,
                                            int kA, int rsA, int qA) {
    float x[16];
#pragma unroll
    for (int j = 0; j < 16; j++) x[j] = ax[j];
    if (BN) {
#pragma unroll
        for (int j = 0; j < 16; j++) {
            float v = fmaf(x[j], g_sc1[kA + j], g_bi1[kA + j]);
            x[j] = (v >= 0.f) ? v : 0.01f*v;
        }
    }
    char* arow = dststage + rsA*PITCH_A + qA*32;
    *(uint4*)arow = make_uint4(pack_h2(x[0], x[1]),  pack_h2(x[2], x[3]),
                               pack_h2(x[4], x[5]),  pack_h2(x[6], x[7]));
    *(uint4*)(arow + 16) = make_uint4(pack_h2(x[8], x[9]),   pack_h2(x[10], x[11]),
                                      pack_h2(x[12], x[13]), pack_h2(x[14], x[15]));
}

template<int KFULL, bool BN>
__device__ __forceinline__ void gemm_core(char* sm, uint32_t sb,
    const float* __restrict__ A, int ldn, int nb,
    const __half* __restrict__ Wh, int ldw, int ob, int kW0,
    float acc[2][4][4])
{
    constexpr int PITCH_B = 2*KFULL + 16;
    constexpr int BSIZE   = 128*PITCH_B;
    constexpr int NK      = KFULL/64;
    constexpr int SEGS    = KFULL/8;          // 16B segments per B row
    int t = threadIdx.x, lane = t & 31, wid = t >> 5;
    int g = wid >> 2, w = wid & 3;
    int tg = t & 127, rsA = tg & 31, qA = tg >> 5;
    // ---- stage B panel once ----
    for (int i = t; i < 128*SEGS; i += 512) {
        int row = i/SEGS, seg = i%SEGS;
        cpa16(sb + row*PITCH_B + seg*16,
              Wh + (size_t)(ob + row)*ldw + kW0 + seg*8);
    }
    CP_COMMIT();
    // ---- A(0) LDG + convert into group stage 0; A(1) prefetch ----
    char*    aBasePtr = sm + BSIZE + g*(2*32*PITCH_A);
    uint32_t aBase    = sb + (uint32_t)(BSIZE + g*(2*32*PITCH_A));
    int nrow = nb + g*32 + rsA;
    float ax[16];
    {
        const float* ap = A + (size_t)(qA*16)*ldn + nrow;
#pragma unroll
        for (int j = 0; j < 16; j++) ax[j] = ap[(size_t)j*ldn];
    }
    conv_storeA<BN>(aBasePtr, ax, qA*16, rsA, qA);
    if (NK > 1) {
        const float* ap = A + (size_t)(64 + qA*16)*ldn + nrow;
#pragma unroll
        for (int j = 0; j < 16; j++) ax[j] = ap[(size_t)j*ldn];
    }
    CP_WAIT(0);
    __syncthreads();   // B panel + everyone's A(0) visible
    uint32_t aOff = (uint32_t)((lane & 15)*PITCH_A + ((lane >> 4) & 1)*16);
    uint32_t bOff = (uint32_t)((w*32 + (lane & 7) + ((lane >> 4) & 1)*8)*PITCH_B
                               + ((lane >> 3) & 1)*16);
    for (int it = 0; it < NK; it++) {
        uint32_t aAddr = aBase + (uint32_t)((it & 1)*32*PITCH_A) + aOff;
        uint32_t bAddr = sb + bOff + (uint32_t)(it*128);
#pragma unroll
        for (int s16 = 0; s16 < 4; s16++) {
            uint32_t Ah[2][4], Bh[2][4];
#pragma unroll
            for (int mt = 0; mt < 2; mt++)
                ldm4(Ah[mt], aAddr + mt*16*PITCH_A + s16*32);
#pragma unroll
            for (int np = 0; np < 2; np++)
                ldm4(Bh[np], bAddr + np*16*PITCH_B + s16*32);
#pragma unroll
            for (int mt = 0; mt < 2; mt++)
#pragma unroll
            for (int nt = 0; nt < 4; nt++)
                mma_f16(acc[mt][nt], Ah[mt], &Bh[nt >> 1][(nt & 1)*2]);
        }
        // stage A(it+1) into other buffer; prefetch A(it+2)
        if (it + 1 < NK) {
            conv_storeA<BN>(aBasePtr + ((it + 1) & 1)*32*PITCH_A, ax,
                            (it + 1)*64 + qA*16, rsA, qA);
            if (it + 2 < NK) {
                const float* ap = A + (size_t)((it + 2)*64 + qA*16)*ldn + nrow;
#pragma unroll
                for (int j = 0; j < 16; j++) ax[j] = ap[(size_t)j*ldn];
            }
        }
        GBAR(1 + g);   // group-scoped: A(it+1) stored, stage (it)&1 free
    }
    __syncthreads();   // all groups done before epilogue overlays A region
}

// dump one 32-o strip into sbuf[o_local][n]  (n = 128, stride 132)
__device__ __forceinline__ void dump_strip(float* sbuf, int s, float acc[2][4][4]) {
    int t = threadIdx.x, lane = t & 31, wid = t >> 5;
    int g = wid >> 2, w = wid & 3;
    if (w != s) return;
    int gr = lane >> 2, c2 = (lane & 3)*2;
#pragma unroll
    for (int mt = 0; mt < 2; mt++)
#pragma unroll
    for (int nt = 0; nt < 4; nt++) {
        int nl = g*32 + mt*16 + gr;
        int ol = nt*8 + c2;
        sbuf[ol*132 + nl]         = acc[mt][nt][0];
        sbuf[(ol+1)*132 + nl]     = acc[mt][nt][1];
        sbuf[ol*132 + nl + 8]     = acc[mt][nt][2];
        sbuf[(ol+1)*132 + nl + 8] = acc[mt][nt][3];
    }
}

// ---------- GEMM 1a: Gt[b][n][o] = W1[:, :512] @ feat ----------
__global__ __launch_bounds__(512, 1)
void gemm1a_kernel(const float* __restrict__ feat) {
    extern __shared__ __align__(16) char sm[];
    constexpr int BSIZE = 128*(2*CPf + 16);
    uint32_t sb = smem_u32(sm);
    int b = blockIdx.z, nb = blockIdx.x*128, ob = blockIdx.y*128;
    int t = threadIdx.x;
    float acc[2][4][4] = {};
    gemm_core<CPf, false>(sm, sb, feat + (size_t)b*CPf*NP, NP, nb,
                          g_W1_h, KW, ob, 0, acc);
    float* sbuf = (float*)(sm + BSIZE + O_SBUF);
    int n = t & 127, oq = t >> 7;
    for (int s = 0; s < 4; s++) {
        __syncthreads();
        dump_strip(sbuf, s, acc);
        __syncthreads();
        float f[8];
#pragma unroll
        for (int j = 0; j < 8; j++) f[j] = sbuf[(oq*8 + j)*132 + n];
        float* dst = &g_Gt[((size_t)b*NP + nb + n)*C1f + ob + s*32 + oq*8];
        *(float4*)dst       = make_float4(f[0], f[1], f[2], f[3]);
        *(float4*)(dst + 4) = make_float4(f[4], f[5], f[6], f[7]);
    }
}

// shared epilogue: optional gather, transpose writeout [o][n], BN-stat partials
__device__ __forceinline__ void epi_write(char* epi, float acc[2][4][4],
                                          float* __restrict__ Y, int nb, int ob,
                                          int b, bool gather) {
    int t = threadIdx.x;
    float* sbuf = (float*)(epi + O_SBUF);
    int*   sid  = (int*)(epi + O_SID);
    float* swt  = (float*)(epi + O_SWT);
    float* chs  = (float*)(epi + O_CHS);
    float* chq  = (float*)(epi + O_CHQ);
    if (gather) {
        for (int i = t; i < 384; i += 512) {
            size_t base = ((size_t)b*N0 + nb)*3 + i;
            sid[i] = g_idx[base]; swt[i] = g_wt[base];
        }
    }
    const float* Gt = g_Gt + (size_t)b*NP*C1f;
    for (int s = 0; s < 4; s++) {
        __syncthreads();
        dump_strip(sbuf, s, acc);
        __syncthreads();
        if (gather) {
            int n = t & 127, oq = t >> 7;
            float v[8];
#pragma unroll
            for (int j = 0; j < 8; j++) v[j] = sbuf[(oq*8 + j)*132 + n];
#pragma unroll
            for (int k = 0; k < 3; k++) {
                int   id = sid[n*3 + k];
                float wk = swt[n*3 + k];
                const float* gp = &Gt[(size_t)id*C1f + ob + s*32 + oq*8];
                float4 g0 = *(const float4*)gp;
                float4 g1 = *(const float4*)(gp + 4);
                v[0] = fmaf(wk, g0.x, v[0]); v[1] = fmaf(wk, g0.y, v[1]);
                v[2] = fmaf(wk, g0.z, v[2]); v[3] = fmaf(wk, g0.w, v[3]);
                v[4] = fmaf(wk, g1.x, v[4]); v[5] = fmaf(wk, g1.y, v[5]);
                v[6] = fmaf(wk, g1.z, v[6]); v[7] = fmaf(wk, g1.w, v[7]);
            }
#pragma unroll
            for (int j = 0; j < 8; j++) sbuf[(oq*8 + j)*132 + n] = v[j];
            __syncthreads();
        }
        {
            int ol = t >> 4, seg = t & 15, n = seg*8;
            const float* srow = &sbuf[ol*132 + n];
            float4 x0 = *(const float4*)srow;
            float4 x1 = *(const float4*)(srow + 4);
            float s1 = x0.x + x0.y + x0.z + x0.w + x1.x + x1.y + x1.z + x1.w;
            float s2 = 0.f;
            s2 = fmaf(x0.x, x0.x, s2); s2 = fmaf(x0.y, x0.y, s2);
            s2 = fmaf(x0.z, x0.z, s2); s2 = fmaf(x0.w, x0.w, s2);
            s2 = fmaf(x1.x, x1.x, s2); s2 = fmaf(x1.y, x1.y, s2);
            s2 = fmaf(x1.z, x1.z, s2); s2 = fmaf(x1.w, x1.w, s2);
            float* dst = &Y[(size_t)(ob + s*32 + ol)*N0 + nb + n];
            *(float4*)dst       = x0;
            *(float4*)(dst + 4) = x1;
#pragma unroll
            for (int off = 8; off; off >>= 1) {
                s1 += __shfl_down_sync(0xffffffffu, s1, off, 16);
                s2 += __shfl_down_sync(0xffffffffu, s2, off, 16);
            }
            if (seg == 0) { chs[s*32 + ol] = s1; chq[s*32 + ol] = s2; }
        }
    }
    __syncthreads();
    if (t < 128) {
        int pidx = blockIdx.x + 64*blockIdx.z;
        g_p1[(size_t)(ob + t)*512 + pidx] = chs[t];
        g_p2[(size_t)(ob + t)*512 + pidx] = chq[t];
    }
}

// ---- GEMM 1b: y1 = W1[:, 512:] @ skip + interp(Gt); fused stats ----
__global__ __launch_bounds__(512, 1)
void gemm1b_kernel(const float* __restrict__ skip) {
    extern __shared__ __align__(16) char sm[];
    constexpr int BSIZE = 128*(2*CSf + 16);
    uint32_t sb = smem_u32(sm);
    int b = blockIdx.z, nb = blockIdx.x*128, ob = blockIdx.y*128;
    float acc[2][4][4] = {};
    gemm_core<CSf, false>(sm, sb, skip + (size_t)b*CSf*N0, N0, nb,
                          g_W1_h, KW, ob, CPf, acc);
    epi_write(sm + BSIZE, acc, g_y1 + (size_t)b*C1f*N0, nb, ob, b, true);
}

// ---- GEMM 2: z = W2 @ lrelu(BN1(y1)); BN on A-stage; fused stats ----
__global__ __launch_bounds__(512, 1)
void gemm2_kernel() {
    extern __shared__ __align__(16) char sm[];
    constexpr int BSIZE = 128*(2*C1f + 16);
    uint32_t sb = smem_u32(sm);
    int b = blockIdx.z, nb = blockIdx.x*128, ob = blockIdx.y*128;
    float acc[2][4][4] = {};
    gemm_core<C1f, true>(sm, sb, g_y1 + (size_t)b*C1f*N0, N0, nb,
                         g_W2_h, C1f, ob, 0, acc);
    epi_write(sm + BSIZE, acc, g_z + (size_t)b*C2f*N0, nb, ob, b, false);
}

// ---------------- stats reduce ----------------
__global__ void stats_reduce(const float* __restrict__ gain,
                             const float* __restrict__ beta, int layer) {
    int o = blockIdx.x, t = threadIdx.x;
    const float* p1 = &g_p1[(size_t)o*512];
    const float* p2 = &g_p2[(size_t)o*512];
    float a = p1[t] + p1[t+128] + p1[t+256] + p1[t+384];
    float c = p2[t] + p2[t+128] + p2[t+256] + p2[t+384];
    __shared__ float r1[128], r2[128];
    r1[t] = a; r2[t] = c; __syncthreads();
    for (int h = 64; h > 0; h >>= 1) {
        if (t < h) { r1[t] += r1[t+h]; r2[t] += r2[t+h]; }
        __syncthreads();
    }
    if (t == 0) {
        const float invN = 1.0f/((float)BB*N0);
        float m   = r1[0]*invN;
        float var = r2[0]*invN - m*m;
        float sc  = gain[o] * (1.0f/sqrtf(var + 1e-3f));
        if (layer) { g_sc2[o] = sc; g_bi2[o] = beta[o] - m*sc; }
        else       { g_sc1[o] = sc; g_bi1[o] = beta[o] - m*sc; }
    }
}

// ---------------- output: lrelu(BN2(z)) ----------------
__global__ void out_kernel(float* __restrict__ out) {
    size_t i = (size_t)blockIdx.x*blockDim.x + threadIdx.x;
    const size_t total4 = (size_t)BB*C2f*N0/4;
    if (i >= total4) return;
    int ch = (int)((i/(N0/4)) % C2f);
    float sc = g_sc2[ch], bi = g_bi2[ch];
    float4 v = *((const float4*)g_z + i);
    v.x = fmaf(v.x, sc, bi); v.x = (v.x >= 0.f) ? v.x : 0.01f*v.x;
    v.y = fmaf(v.y, sc, bi); v.y = (v.y >= 0.f) ? v.y : 0.01f*v.y;
    v.z = fmaf(v.z, sc, bi); v.z = (v.z >= 0.f) ? v.z : 0.01f*v.z;
    v.w = fmaf(v.w, sc, bi); v.w = (v.w >= 0.f) ? v.w : 0.01f*v.w;
    *((float4*)out + i) = v;
}

// ---------------- launch ----------------
extern "C" void kernel_launch(void* const* d_in, const int* in_sizes, int n_in,
                              void* d_out, int out_size) {
    const float* xyz   = (const float*)d_in[0];
    const float* skip  = (const float*)d_in[1];
    const float* xyzp  = (const float*)d_in[2];
    const float* featp = (const float*)d_in[3];
    const float* W1    = (const float*)d_in[4];
    const float* g1    = (const float*)d_in[5];
    const float* b1    = (const float*)d_in[6];
    const float* W2    = (const float*)d_in[7];
    const float* g2    = (const float*)d_in[8];
    const float* b2    = (const float*)d_in[9];
    float* out = (float*)d_out;

    const int SM1A = 128*(2*CPf + 16) + EPI_BYTES;   // 169984
    const int SM1B = 128*(2*CSf + 16) + EPI_BYTES;   // 104448
    const int SM2  = 128*(2*C1f + 16) + EPI_BYTES;   // 104448

    static int s_attr = 0;
    if (!s_attr) {
        cudaFuncSetAttribute(gemm1a_kernel, cudaFuncAttributeMaxDynamicSharedMemorySize, SM1A);
        cudaFuncSetAttribute(gemm1b_kernel, cudaFuncAttributeMaxDynamicSharedMemorySize, SM1B);
        cudaFuncSetAttribute(gemm2_kernel,  cudaFuncAttributeMaxDynamicSharedMemorySize, SM2);
        s_attr = 1;
    }

    __half *w1_h, *w2_h;
    cudaGetSymbolAddress((void**)&w1_h, g_W1_h);
    cudaGetSymbolAddress((void**)&w2_h, g_W2_h);

    const size_t xyz_elems = (size_t)BB*3*N0;
    const size_t nf_elems  = (size_t)BB*C2f*N0;
    size_t off = 0;
    if ((size_t)out_size >= xyz_elems + nf_elems) {
        cudaMemcpyAsync(out, xyz, xyz_elems*sizeof(float), cudaMemcpyDeviceToDevice);
        off = xyz_elems;
    }

    knn_kernel   <<<dim3(N0/256, BB), 256>>>(xyz, xyzp);
    wconv_kernel <<<(C1f*KW/2 + 255)/256,  256>>>(W1, w1_h, C1f*KW/2);
    wconv_kernel <<<(C2f*C1f/2 + 255)/256, 256>>>(W2, w2_h, C2f*C1f/2);
    gemm1a_kernel<<<dim3(NP/128, C1f/128, BB), 512, SM1A>>>(featp);
    gemm1b_kernel<<<dim3(N0/128, C1f/128, BB), 512, SM1B>>>(skip);
    stats_reduce <<<C1f, 128>>>(g1, b1, 0);
    gemm2_kernel <<<dim3(N0/128, C2f/128, BB), 512, SM2>>>();
    stats_reduce <<<C2f, 128>>>(g2, b2, 1);
    out_kernel   <<<(unsigned)((nf_elems/4 + 255)/256), 256>>>(out + off);
}

// round 13
// speedup vs baseline: 1.0915x; 1.0403x over previous
#include <cuda_runtime.h>
#include <cuda_fp16.h>
#include <cstdint>

#define BB  8
#define N0  8192
#define NP  2048
#define CPf 512
#define CSf 256
#define C1f 256
#define C2f 256
#define KW  768   // CP+CS

#define PITCH_A 144              // 64 fp16 + 16B pad
#define EPI_BYTES 36864
// epilogue overlay offsets (relative to A-region base = B panel size)
#define O_SBUF 0                 // 32 x 132 floats = 16896
#define O_SID  16896             // 384 int
#define O_SWT  18432             // 384 float
#define O_CHS  19968             // 128 float
#define O_CHQ  20480             // 128 float

// ---------------- scratch (device globals) ----------------
__device__ int    g_idx[BB*N0*3];
__device__ float  g_wt [BB*N0*3];
__device__ float  g_Gt [BB*NP*C1f];
__device__ __align__(16) __half g_y1[BB*C1f*N0];   // fp16 pre-BN layer-1 output
__device__ __align__(16) __half g_z [BB*C2f*N0];   // fp16 pre-BN layer-2 output
__device__ float  g_p1 [C1f*512], g_p2[C1f*512];
__device__ float  g_sc1[C1f], g_bi1[C1f], g_sc2[C2f], g_bi2[C2f];
__device__ __align__(16) __half g_W1_h[C1f*KW];
__device__ __align__(16) __half g_W2_h[C2f*C1f];

// ---------------- PTX wrappers ----------------
__device__ __forceinline__ uint32_t smem_u32(const void* p) {
    uint32_t a;
    asm("{ .reg .u64 t; cvta.to.shared.u64 t, %1; cvt.u32.u64 %0, t; }" : "=r"(a) : "l"(p));
    return a;
}
__device__ __forceinline__ void ldm4(uint32_t* r, uint32_t addr) {
    asm volatile("ldmatrix.sync.aligned.m8n8.x4.shared.b16 {%0,%1,%2,%3}, [%4];"
        : "=r"(r[0]), "=r"(r[1]), "=r"(r[2]), "=r"(r[3]) : "r"(addr));
}
__device__ __forceinline__ void mma_f16(float* d, const uint32_t* a, const uint32_t* b) {
    asm volatile("mma.sync.aligned.m16n8k16.row.col.f32.f16.f16.f32 "
        "{%0,%1,%2,%3}, {%4,%5,%6,%7}, {%8,%9}, {%0,%1,%2,%3};"
        : "+f"(d[0]), "+f"(d[1]), "+f"(d[2]), "+f"(d[3])
        : "r"(a[0]), "r"(a[1]), "r"(a[2]), "r"(a[3]), "r"(b[0]), "r"(b[1]));
}
__device__ __forceinline__ uint32_t pack_h2(float a, float b) {
    __half2 p = __floats2half2_rn(a, b);
    return *(uint32_t*)&p;
}
__device__ __forceinline__ void cpa16(uint32_t dst, const void* src) {
    asm volatile("cp.async.cg.shared.global [%0], [%1], 16;" :: "r"(dst), "l"(src) : "memory");
}
#define CP_COMMIT() asm volatile("cp.async.commit_group;" ::: "memory")
#define CP_WAIT(n)  asm volatile("cp.async.wait_group %0;" :: "n"(n) : "memory")
#define GBAR(id)    asm volatile("bar.sync %0, 128;" :: "r"(id) : "memory")

// ---------------- kNN (512 threads, 128 CTAs = 1 full wave) ----------------
__global__ void knn_kernel(const float* __restrict__ xyz,
                           const float* __restrict__ xyzp) {
    __shared__ float4 sp[NP];
    int b = blockIdx.y;
    const float* p = xyzp + (size_t)b*3*NP;
    for (int j = threadIdx.x; j < NP; j += blockDim.x) {
        float X = p[j], Y = p[NP + j], Z = p[2*NP + j];
        sp[j] = make_float4(X, Y, Z, X*X + Y*Y + Z*Z);
    }
    __syncthreads();
    int n = blockIdx.x*blockDim.x + threadIdx.x;
    const float* q = xyz + (size_t)b*3*N0;
    float qx = q[n], qy = q[N0 + n], qz = q[2*N0 + n];
    float q2 = qx*qx + qy*qy + qz*qz;
    float d0 = 1e30f, d1 = 1e30f, d2 = 1e30f;
    int   i0 = 0, i1 = 0, i2 = 0;
#pragma unroll 4
    for (int j = 0; j < NP; ++j) {
        float4 v = sp[j];
        float dot = qx*v.x + qy*v.y + qz*v.z;
        float d = (q2 + v.w) - 2.0f*dot;
        if (d < d2) {
            if (d < d1) {
                d2 = d1; i2 = i1;
                if (d < d0) { d1 = d0; i1 = i0; d0 = d; i0 = j; }
                else        { d1 = d;  i1 = j; }
            } else { d2 = d; i2 = j; }
        }
    }
    float e0 = 1.0f/(fmaxf(d0, 1e-10f) + 1e-8f);
    float e1 = 1.0f/(fmaxf(d1, 1e-10f) + 1e-8f);
    float e2 = 1.0f/(fmaxf(d2, 1e-10f) + 1e-8f);
    float inv = 1.0f/(e0 + e1 + e2);
    size_t base = ((size_t)b*N0 + n)*3;
    g_idx[base]   = i0; g_idx[base+1] = i1; g_idx[base+2] = i2;
    g_wt [base]   = e0*inv; g_wt[base+1] = e1*inv; g_wt[base+2] = e2*inv;
}

// ---------------- weight convert ----------------
__global__ void wconv_kernel(const float* __restrict__ w,
                             __half* __restrict__ hi, int npairs) {
    int i = blockIdx.x*blockDim.x + threadIdx.x;
    if (i >= npairs) return;
    ((uint32_t*)hi)[i] = pack_h2(w[2*i], w[2*i + 1]);
}

// ===================== fp16 mma.sync GEMM core =====================
// 512 threads, 16 warps = 4 groups x 4 warps. Group g owns n-rows [g*32, g*32+32),
// warp w in group owns o-cols [w*32, w*32+32). B panel (128o x KFULL) staged once.
// A double-buffered per group; one named barrier (4 warps) per 64-K chunk.

template<bool BN>
__device__ __forceinline__ void conv_storeA(char* dststage, const float* ax,
                                            int kA, int rsA, int qA) {
    float x[16];
#pragma unroll
    for (int j = 0; j < 16; j++) x[j] = ax[j];
    if (BN) {
#pragma unroll
        for (int j = 0; j < 16; j++) {
            float v = fmaf(x[j], g_sc1[kA + j], g_bi1[kA + j]);
            x[j] = (v >= 0.f) ? v : 0.01f*v;
        }
    }
    char* arow = dststage + rsA*PITCH_A + qA*32;
    *(uint4*)arow = make_uint4(pack_h2(x[0], x[1]),  pack_h2(x[2], x[3]),
                               pack_h2(x[4], x[5]),  pack_h2(x[6], x[7]));
    *(uint4*)(arow + 16) = make_uint4(pack_h2(x[8], x[9]),   pack_h2(x[10], x[11]),
                                      pack_h2(x[12], x[13]), pack_h2(x[14], x[15]));
}

template<int KFULL, bool BN, typename AT>
__device__ __forceinline__ void gemm_core(char* sm, uint32_t sb,
    const AT* __restrict__ A, int ldn, int nb,
    const __half* __restrict__ Wh, int ldw, int ob, int kW0,
    float acc[2][4][4])
{
    constexpr int PITCH_B = 2*KFULL + 16;
    constexpr int BSIZE   = 128*PITCH_B;
    constexpr int NK      = KFULL/64;
    constexpr int SEGS    = KFULL/8;          // 16B segments per B row
    int t = threadIdx.x, lane = t & 31, wid = t >> 5;
    int g = wid >> 2, w = wid & 3;
    int tg = t & 127, rsA = tg & 31, qA = tg >> 5;
    // ---- stage B panel once ----
    for (int i = t; i < 128*SEGS; i += 512) {
        int row = i/SEGS, seg = i%SEGS;
        cpa16(sb + row*PITCH_B + seg*16,
              Wh + (size_t)(ob + row)*ldw + kW0 + seg*8);
    }
    CP_COMMIT();
    // ---- A(0) LDG + convert into group stage 0; A(1) prefetch ----
    char*    aBasePtr = sm + BSIZE + g*(2*32*PITCH_A);
    uint32_t aBase    = sb + (uint32_t)(BSIZE + g*(2*32*PITCH_A));
    int nrow = nb + g*32 + rsA;
    float ax[16];
    {
        const AT* ap = A + (size_t)(qA*16)*ldn + nrow;
#pragma unroll
        for (int j = 0; j < 16; j++) ax[j] = (float)ap[(size_t)j*ldn];
    }
    conv_storeA<BN>(aBasePtr, ax, qA*16, rsA, qA);
    if (NK > 1) {
        const AT* ap = A + (size_t)(64 + qA*16)*ldn + nrow;
#pragma unroll
        for (int j = 0; j < 16; j++) ax[j] = (float)ap[(size_t)j*ldn];
    }
    CP_WAIT(0);
    __syncthreads();   // B panel + everyone's A(0) visible
    uint32_t aOff = (uint32_t)((lane & 15)*PITCH_A + ((lane >> 4) & 1)*16);
    uint32_t bOff = (uint32_t)((w*32 + (lane & 7) + ((lane >> 4) & 1)*8)*PITCH_B
                               + ((lane >> 3) & 1)*16);
    for (int it = 0; it < NK; it++) {
        uint32_t aAddr = aBase + (uint32_t)((it & 1)*32*PITCH_A) + aOff;
        uint32_t bAddr = sb + bOff + (uint32_t)(it*128);
#pragma unroll
        for (int s16 = 0; s16 < 4; s16++) {
            uint32_t Ah[2][4], Bh[2][4];
#pragma unroll
            for (int mt = 0; mt < 2; mt++)
                ldm4(Ah[mt], aAddr + mt*16*PITCH_A + s16*32);
#pragma unroll
            for (int np = 0; np < 2; np++)
                ldm4(Bh[np], bAddr + np*16*PITCH_B + s16*32);
#pragma unroll
            for (int mt = 0; mt < 2; mt++)
#pragma unroll
            for (int nt = 0; nt < 4; nt++)
                mma_f16(acc[mt][nt], Ah[mt], &Bh[nt >> 1][(nt & 1)*2]);
        }
        // stage A(it+1) into other buffer; prefetch A(it+2)
        if (it + 1 < NK) {
            conv_storeA<BN>(aBasePtr + ((it + 1) & 1)*32*PITCH_A, ax,
                            (it + 1)*64 + qA*16, rsA, qA);
            if (it + 2 < NK) {
                const AT* ap = A + (size_t)((it + 2)*64 + qA*16)*ldn + nrow;
#pragma unroll
                for (int j = 0; j < 16; j++) ax[j] = (float)ap[(size_t)j*ldn];
            }
        }
        GBAR(1 + g);   // group-scoped: A(it+1) stored, stage (it)&1 free
    }
    __syncthreads();   // all groups done before epilogue overlays A region
}

// dump one 32-o strip into sbuf[o_local][n]  (n = 128, stride 132)
__device__ __forceinline__ void dump_strip(float* sbuf, int s, float acc[2][4][4]) {
    int t = threadIdx.x, lane = t & 31, wid = t >> 5;
    int g = wid >> 2, w = wid & 3;
    if (w != s) return;
    int gr = lane >> 2, c2 = (lane & 3)*2;
#pragma unroll
    for (int mt = 0; mt < 2; mt++)
#pragma unroll
    for (int nt = 0; nt < 4; nt++) {
        int nl = g*32 + mt*16 + gr;
        int ol = nt*8 + c2;
        sbuf[ol*132 + nl]         = acc[mt][nt][0];
        sbuf[(ol+1)*132 + nl]     = acc[mt][nt][1];
        sbuf[ol*132 + nl + 8]     = acc[mt][nt][2];
        sbuf[(ol+1)*132 + nl + 8] = acc[mt][nt][3];
    }
}

// ---------- GEMM 1a: Gt[b][n][o] = W1[:, :512] @ feat (fp32 out for gather) ----------
__global__ __launch_bounds__(512, 1)
void gemm1a_kernel(const float* __restrict__ feat) {
    extern __shared__ __align__(16) char sm[];
    constexpr int BSIZE = 128*(2*CPf + 16);
    uint32_t sb = smem_u32(sm);
    int b = blockIdx.z, nb = blockIdx.x*128, ob = blockIdx.y*128;
    int t = threadIdx.x;
    float acc[2][4][4] = {};
    gemm_core<CPf, false, float>(sm, sb, feat + (size_t)b*CPf*NP, NP, nb,
                                 g_W1_h, KW, ob, 0, acc);
    float* sbuf = (float*)(sm + BSIZE + O_SBUF);
    int n = t & 127, oq = t >> 7;
    for (int s = 0; s < 4; s++) {
        __syncthreads();
        dump_strip(sbuf, s, acc);
        __syncthreads();
        float f[8];
#pragma unroll
        for (int j = 0; j < 8; j++) f[j] = sbuf[(oq*8 + j)*132 + n];
        float* dst = &g_Gt[((size_t)b*NP + nb + n)*C1f + ob + s*32 + oq*8];
        *(float4*)dst       = make_float4(f[0], f[1], f[2], f[3]);
        *(float4*)(dst + 4) = make_float4(f[4], f[5], f[6], f[7]);
    }
}

// shared epilogue: optional gather, transpose writeout [o][n] (fp16), BN-stat partials
__device__ __forceinline__ void epi_write(char* epi, float acc[2][4][4],
                                          __half* __restrict__ Y, int nb, int ob,
                                          int b, bool gather) {
    int t = threadIdx.x;
    float* sbuf = (float*)(epi + O_SBUF);
    int*   sid  = (int*)(epi + O_SID);
    float* swt  = (float*)(epi + O_SWT);
    float* chs  = (float*)(epi + O_CHS);
    float* chq  = (float*)(epi + O_CHQ);
    if (gather) {
        for (int i = t; i < 384; i += 512) {
            size_t base = ((size_t)b*N0 + nb)*3 + i;
            sid[i] = g_idx[base]; swt[i] = g_wt[base];
        }
    }
    const float* Gt = g_Gt + (size_t)b*NP*C1f;
    for (int s = 0; s < 4; s++) {
        __syncthreads();
        dump_strip(sbuf, s, acc);
        __syncthreads();
        if (gather) {
            int n = t & 127, oq = t >> 7;
            float v[8];
#pragma unroll
            for (int j = 0; j < 8; j++) v[j] = sbuf[(oq*8 + j)*132 + n];
#pragma unroll
            for (int k = 0; k < 3; k++) {
                int   id = sid[n*3 + k];
                float wk = swt[n*3 + k];
                const float* gp = &Gt[(size_t)id*C1f + ob + s*32 + oq*8];
                float4 g0 = *(const float4*)gp;
                float4 g1 = *(const float4*)(gp + 4);
                v[0] = fmaf(wk, g0.x, v[0]); v[1] = fmaf(wk, g0.y, v[1]);
                v[2] = fmaf(wk, g0.z, v[2]); v[3] = fmaf(wk, g0.w, v[3]);
                v[4] = fmaf(wk, g1.x, v[4]); v[5] = fmaf(wk, g1.y, v[5]);
                v[6] = fmaf(wk, g1.z, v[6]); v[7] = fmaf(wk, g1.w, v[7]);
            }
#pragma unroll
            for (int j = 0; j < 8; j++) sbuf[(oq*8 + j)*132 + n] = v[j];
            __syncthreads();
        }
        {
            int ol = t >> 4, seg = t & 15, n = seg*8;
            const float* srow = &sbuf[ol*132 + n];
            float4 x0 = *(const float4*)srow;
            float4 x1 = *(const float4*)(srow + 4);
            float s1 = x0.x + x0.y + x0.z + x0.w + x1.x + x1.y + x1.z + x1.w;
            float s2 = 0.f;
            s2 = fmaf(x0.x, x0.x, s2); s2 = fmaf(x0.y, x0.y, s2);
            s2 = fmaf(x0.z, x0.z, s2); s2 = fmaf(x0.w, x0.w, s2);
            s2 = fmaf(x1.x, x1.x, s2); s2 = fmaf(x1.y, x1.y, s2);
            s2 = fmaf(x1.z, x1.z, s2); s2 = fmaf(x1.w, x1.w, s2);
            __half* dst = &Y[(size_t)(ob + s*32 + ol)*N0 + nb + n];
            *(uint4*)dst = make_uint4(pack_h2(x0.x, x0.y), pack_h2(x0.z, x0.w),
                                      pack_h2(x1.x, x1.y), pack_h2(x1.z, x1.w));
#pragma unroll
            for (int off = 8; off; off >>= 1) {
                s1 += __shfl_down_sync(0xffffffffu, s1, off, 16);
                s2 += __shfl_down_sync(0xffffffffu, s2, off, 16);
            }
            if (seg == 0) { chs[s*32 + ol] = s1; chq[s*32 + ol] = s2; }
        }
    }
    __syncthreads();
    if (t < 128) {
        int pidx = blockIdx.x + 64*blockIdx.z;
        g_p1[(size_t)(ob + t)*512 + pidx] = chs[t];
        g_p2[(size_t)(ob + t)*512 + pidx] = chq[t];
    }
}

// ---- GEMM 1b: y1 = W1[:, 512:] @ skip + interp(Gt); fused stats; fp16 out ----
__global__ __launch_bounds__(512, 1)
void gemm1b_kernel(const float* __restrict__ skip) {
    extern __shared__ __align__(16) char sm[];
    constexpr int BSIZE = 128*(2*CSf + 16);
    uint32_t sb = smem_u32(sm);
    int b = blockIdx.z, nb = blockIdx.x*128, ob = blockIdx.y*128;
    float acc[2][4][4] = {};
    gemm_core<CSf, false, float>(sm, sb, skip + (size_t)b*CSf*N0, N0, nb,
                                 g_W1_h, KW, ob, CPf, acc);
    epi_write(sm + BSIZE, acc, g_y1 + (size_t)b*C1f*N0, nb, ob, b, true);
}

// ---- GEMM 2: z = W2 @ lrelu(BN1(y1)); y1 fp16 in, BN on A-stage; fp16 out ----
__global__ __launch_bounds__(512, 1)
void gemm2_kernel() {
    extern __shared__ __align__(16) char sm[];
    constexpr int BSIZE = 128*(2*C1f + 16);
    uint32_t sb = smem_u32(sm);
    int b = blockIdx.z, nb = blockIdx.x*128, ob = blockIdx.y*128;
    float acc[2][4][4] = {};
    gemm_core<C1f, true, __half>(sm, sb, g_y1 + (size_t)b*C1f*N0, N0, nb,
                                 g_W2_h, C1f, ob, 0, acc);
    epi_write(sm + BSIZE, acc, g_z + (size_t)b*C2f*N0, nb, ob, b, false);
}

// ---------------- stats reduce ----------------
__global__ void stats_reduce(const float* __restrict__ gain,
                             const float* __restrict__ beta, int layer) {
    int o = blockIdx.x, t = threadIdx.x;
    const float* p1 = &g_p1[(size_t)o*512];
    const float* p2 = &g_p2[(size_t)o*512];
    float a = p1[t] + p1[t+128] + p1[t+256] + p1[t+384];
    float c = p2[t] + p2[t+128] + p2[t+256] + p2[t+384];
    __shared__ float r1[128], r2[128];
    r1[t] = a; r2[t] = c; __syncthreads();
    for (int h = 64; h > 0; h >>= 1) {
        if (t < h) { r1[t] += r1[t+h]; r2[t] += r2[t+h]; }
        __syncthreads();
    }
    if (t == 0) {
        const float invN = 1.0f/((float)BB*N0);
        float m   = r1[0]*invN;
        float var = r2[0]*invN - m*m;
        float sc  = gain[o] * (1.0f/sqrtf(var + 1e-3f));
        if (layer) { g_sc2[o] = sc; g_bi2[o] = beta[o] - m*sc; }
        else       { g_sc1[o] = sc; g_bi1[o] = beta[o] - m*sc; }
    }
}

// ---------------- output: lrelu(BN2(z)), fp16 z -> fp32 out ----------------
__global__ void out_kernel(float* __restrict__ out) {
    size_t i = (size_t)blockIdx.x*blockDim.x + threadIdx.x;   // 8-half groups
    const size_t total8 = (size_t)BB*C2f*N0/8;
    if (i >= total8) return;
    int ch = (int)((i >> 10) & (C2f - 1));                    // N0/8 = 1024 groups/row
    float sc = g_sc2[ch], bi = g_bi2[ch];
    uint4 hv = *((const uint4*)g_z + i);
    float f[8];
    {
        __half2 h;
        *(uint32_t*)&h = hv.x; f[0] = __low2float(h); f[1] = __high2float(h);
        *(uint32_t*)&h = hv.y; f[2] = __low2float(h); f[3] = __high2float(h);
        *(uint32_t*)&h = hv.z; f[4] = __low2float(h); f[5] = __high2float(h);
        *(uint32_t*)&h = hv.w; f[6] = __low2float(h); f[7] = __high2float(h);
    }
#pragma unroll
    for (int j = 0; j < 8; j++) {
        float v = fmaf(f[j], sc, bi);
        f[j] = (v >= 0.f) ? v : 0.01f*v;
    }
    float* dst = out + i*8;
    *(float4*)dst       = make_float4(f[0], f[1], f[2], f[3]);
    *(float4*)(dst + 4) = make_float4(f[4], f[5], f[6], f[7]);
}

// ---------------- launch ----------------
extern "C" void kernel_launch(void* const* d_in, const int* in_sizes, int n_in,
                              void* d_out, int out_size) {
    const float* xyz   = (const float*)d_in[0];
    const float* skip  = (const float*)d_in[1];
    const float* xyzp  = (const float*)d_in[2];
    const float* featp = (const float*)d_in[3];
    const float* W1    = (const float*)d_in[4];
    const float* g1    = (const float*)d_in[5];
    const float* b1    = (const float*)d_in[6];
    const float* W2    = (const float*)d_in[7];
    const float* g2    = (const float*)d_in[8];
    const float* b2    = (const float*)d_in[9];
    float* out = (float*)d_out;

    const int SM1A = 128*(2*CPf + 16) + EPI_BYTES;   // 169984
    const int SM1B = 128*(2*CSf + 16) + EPI_BYTES;   // 104448
    const int SM2  = 128*(2*C1f + 16) + EPI_BYTES;   // 104448

    static int s_attr = 0;
    if (!s_attr) {
        cudaFuncSetAttribute(gemm1a_kernel, cudaFuncAttributeMaxDynamicSharedMemorySize, SM1A);
        cudaFuncSetAttribute(gemm1b_kernel, cudaFuncAttributeMaxDynamicSharedMemorySize, SM1B);
        cudaFuncSetAttribute(gemm2_kernel,  cudaFuncAttributeMaxDynamicSharedMemorySize, SM2);
        s_attr = 1;
    }

    __half *w1_h, *w2_h;
    cudaGetSymbolAddress((void**)&w1_h, g_W1_h);
    cudaGetSymbolAddress((void**)&w2_h, g_W2_h);

    const size_t xyz_elems = (size_t)BB*3*N0;
    const size_t nf_elems  = (size_t)BB*C2f*N0;
    size_t off = 0;
    if ((size_t)out_size >= xyz_elems + nf_elems) {
        cudaMemcpyAsync(out, xyz, xyz_elems*sizeof(float), cudaMemcpyDeviceToDevice);
        off = xyz_elems;
    }

    knn_kernel   <<<dim3(N0/512, BB), 512>>>(xyz, xyzp);
    wconv_kernel <<<(C1f*KW/2 + 255)/256,  256>>>(W1, w1_h, C1f*KW/2);
    wconv_kernel <<<(C2f*C1f/2 + 255)/256, 256>>>(W2, w2_h, C2f*C1f/2);
    gemm1a_kernel<<<dim3(NP/128, C1f/128, BB), 512, SM1A>>>(featp);
    gemm1b_kernel<<<dim3(N0/128, C1f/128, BB), 512, SM1B>>>(skip);
    stats_reduce <<<C1f, 128>>>(g1, b1, 0);
    gemm2_kernel <<<dim3(N0/128, C2f/128, BB), 512, SM2>>>();
    stats_reduce <<<C2f, 128>>>(g2, b2, 1);
    out_kernel   <<<(unsigned)((nf_elems/8 + 255)/256), 256>>>(out + off);
}

// round 14
// speedup vs baseline: 1.2845x; 1.1769x over previous
#include <cuda_runtime.h>
#include <cuda_fp16.h>
#include <cstdint>

#define BB  8
#define N0  8192
#define NP  2048
#define CPf 512
#define CSf 256
#define C1f 256
#define C2f 256
#define KW  768   // CP+CS

#define PITCH_A 144              // 64 fp16 + 16B pad
#define EPI_BYTES 36864
// epilogue overlay offsets (relative to A-region base = B panel size)
#define O_SBUF 0                 // 32 x 132 floats = 16896
#define O_SID  16896             // 384 int
#define O_SWT  18432             // 384 float
#define O_CHS  19968             // 128 float
#define O_CHQ  20480             // 128 float

// ---------------- scratch (device globals) ----------------
__device__ int    g_idx[BB*N0*3];
__device__ float  g_wt [BB*N0*3];
__device__ __align__(16) __half g_Gt[BB*NP*C1f];   // fp16 interp source
__device__ __align__(16) __half g_y1[BB*C1f*N0];   // fp16 pre-BN layer-1 output
__device__ __align__(16) __half g_z [BB*C2f*N0];   // fp16 pre-BN layer-2 output
__device__ float  g_p1 [C1f*512], g_p2[C1f*512];
__device__ float  g_sc1[C1f], g_bi1[C1f], g_sc2[C2f], g_bi2[C2f];
__device__ __align__(16) __half g_W1_h[C1f*KW];
__device__ __align__(16) __half g_W2_h[C2f*C1f];

// ---------------- PTX wrappers ----------------
__device__ __forceinline__ uint32_t smem_u32(const void* p) {
    uint32_t a;
    asm("{ .reg .u64 t; cvta.to.shared.u64 t, %1; cvt.u32.u64 %0, t; }" : "=r"(a) : "l"(p));
    return a;
}
__device__ __forceinline__ void ldm4(uint32_t* r, uint32_t addr) {
    asm volatile("ldmatrix.sync.aligned.m8n8.x4.shared.b16 {%0,%1,%2,%3}, [%4];"
        : "=r"(r[0]), "=r"(r[1]), "=r"(r[2]), "=r"(r[3]) : "r"(addr));
}
__device__ __forceinline__ void mma_f16(float* d, const uint32_t* a, const uint32_t* b) {
    asm volatile("mma.sync.aligned.m16n8k16.row.col.f32.f16.f16.f32 "
        "{%0,%1,%2,%3}, {%4,%5,%6,%7}, {%8,%9}, {%0,%1,%2,%3};"
        : "+f"(d[0]), "+f"(d[1]), "+f"(d[2]), "+f"(d[3])
        : "r"(a[0]), "r"(a[1]), "r"(a[2]), "r"(a[3]), "r"(b[0]), "r"(b[1]));
}
__device__ __forceinline__ uint32_t pack_h2(float a, float b) {
    __half2 p = __floats2half2_rn(a, b);
    return *(uint32_t*)&p;
}
__device__ __forceinline__ void cpa16(uint32_t dst, const void* src) {
    asm volatile("cp.async.cg.shared.global [%0], [%1], 16;" :: "r"(dst), "l"(src) : "memory");
}
#define CP_COMMIT() asm volatile("cp.async.commit_group;" ::: "memory")
#define CP_WAIT(n)  asm volatile("cp.async.wait_group %0;" :: "n"(n) : "memory")
#define GBAR(id)    asm volatile("bar.sync %0, 128;" :: "r"(id) : "memory")

// ---------------- weight convert ----------------
__global__ void wconv_kernel(const float* __restrict__ w,
                             __half* __restrict__ hi, int npairs) {
    int i = blockIdx.x*blockDim.x + threadIdx.x;
    if (i >= npairs) return;
    ((uint32_t*)hi)[i] = pack_h2(w[2*i], w[2*i + 1]);
}

// ===================== kNN body (shifted-distance) =====================
__device__ __forceinline__ void knn_body(char* sm, const float* __restrict__ xyz,
                                         const float* __restrict__ xyzp, int kb) {
    float4* sp = (float4*)sm;        // 2048 * 16B = 32 KB
    int b = kb >> 4, nb = (kb & 15) << 9;
    int t = threadIdx.x;
    const float* p = xyzp + (size_t)b*3*NP;
    for (int j = t; j < NP; j += 512) {
        float X = p[j], Y = p[NP + j], Z = p[2*NP + j];
        sp[j] = make_float4(-2.f*X, -2.f*Y, -2.f*Z, X*X + Y*Y + Z*Z);
    }
    __syncthreads();
    int n = nb + t;
    const float* q = xyz + (size_t)b*3*N0;
    float qx = q[n], qy = q[N0 + n], qz = q[2*N0 + n];
    float q2 = qx*qx + qy*qy + qz*qz;
    float d0 = 1e30f, d1 = 1e30f, d2 = 1e30f;   // shifted keys (d - q2)
    int   i0 = 0, i1 = 0, i2 = 0;
#pragma unroll 4
    for (int j = 0; j < NP; ++j) {
        float4 v = sp[j];
        float d = fmaf(qx, v.x, fmaf(qy, v.y, fmaf(qz, v.z, v.w)));
        if (d < d2) {
            if (d < d1) {
                d2 = d1; i2 = i1;
                if (d < d0) { d1 = d0; i1 = i0; d0 = d; i0 = j; }
                else        { d1 = d;  i1 = j; }
            } else { d2 = d; i2 = j; }
        }
    }
    float e0 = 1.0f/(fmaxf(d0 + q2, 1e-10f) + 1e-8f);
    float e1 = 1.0f/(fmaxf(d1 + q2, 1e-10f) + 1e-8f);
    float e2 = 1.0f/(fmaxf(d2 + q2, 1e-10f) + 1e-8f);
    float inv = 1.0f/(e0 + e1 + e2);
    size_t base = ((size_t)b*N0 + n)*3;
    g_idx[base]   = i0; g_idx[base+1] = i1; g_idx[base+2] = i2;
    g_wt [base]   = e0*inv; g_wt[base+1] = e1*inv; g_wt[base+2] = e2*inv;
}

// ===================== fp16 mma.sync GEMM core =====================
// 512 threads, 16 warps = 4 groups x 4 warps. Group g owns n-rows [g*32, g*32+32),
// warp w in group owns o-cols [w*32, w*32+32). B panel (128o x KFULL) staged once.
// A double-buffered per group; one named barrier (4 warps) per 64-K chunk.

template<bool BN>
__device__ __forceinline__ void conv_storeA(char* dststage, const float* ax,
                                            int kA, int rsA, int qA) {
    float x[16];
#pragma unroll
    for (int j = 0; j < 16; j++) x[j] = ax[j];
    if (BN) {
#pragma unroll
        for (int j = 0; j < 16; j++) {
            float v = fmaf(x[j], g_sc1[kA + j], g_bi1[kA + j]);
            x[j] = (v >= 0.f) ? v : 0.01f*v;
        }
    }
    char* arow = dststage + rsA*PITCH_A + qA*32;
    *(uint4*)arow = make_uint4(pack_h2(x[0], x[1]),  pack_h2(x[2], x[3]),
                               pack_h2(x[4], x[5]),  pack_h2(x[6], x[7]));
    *(uint4*)(arow + 16) = make_uint4(pack_h2(x[8], x[9]),   pack_h2(x[10], x[11]),
                                      pack_h2(x[12], x[13]), pack_h2(x[14], x[15]));
}

template<int KFULL, bool BN, typename AT>
__device__ __forceinline__ void gemm_core(char* sm, uint32_t sb,
    const AT* __restrict__ A, int ldn, int nb,
    const __half* __restrict__ Wh, int ldw, int ob, int kW0,
    float acc[2][4][4])
{
    constexpr int PITCH_B = 2*KFULL + 16;
    constexpr int BSIZE   = 128*PITCH_B;
    constexpr int NK      = KFULL/64;
    constexpr int SEGS    = KFULL/8;          // 16B segments per B row
    int t = threadIdx.x, lane = t & 31, wid = t >> 5;
    int g = wid >> 2, w = wid & 3;
    int tg = t & 127, rsA = tg & 31, qA = tg >> 5;
    // ---- stage B panel once ----
    for (int i = t; i < 128*SEGS; i += 512) {
        int row = i/SEGS, seg = i%SEGS;
        cpa16(sb + row*PITCH_B + seg*16,
              Wh + (size_t)(ob + row)*ldw + kW0 + seg*8);
    }
    CP_COMMIT();
    // ---- A(0) LDG + convert into group stage 0; A(1) prefetch ----
    char*    aBasePtr = sm + BSIZE + g*(2*32*PITCH_A);
    uint32_t aBase    = sb + (uint32_t)(BSIZE + g*(2*32*PITCH_A));
    int nrow = nb + g*32 + rsA;
    float ax[16];
    {
        const AT* ap = A + (size_t)(qA*16)*ldn + nrow;
#pragma unroll
        for (int j = 0; j < 16; j++) ax[j] = (float)ap[(size_t)j*ldn];
    }
    conv_storeA<BN>(aBasePtr, ax, qA*16, rsA, qA);
    if (NK > 1) {
        const AT* ap = A + (size_t)(64 + qA*16)*ldn + nrow;
#pragma unroll
        for (int j = 0; j < 16; j++) ax[j] = (float)ap[(size_t)j*ldn];
    }
    CP_WAIT(0);
    __syncthreads();   // B panel + everyone's A(0) visible
    uint32_t aOff = (uint32_t)((lane & 15)*PITCH_A + ((lane >> 4) & 1)*16);
    uint32_t bOff = (uint32_t)((w*32 + (lane & 7) + ((lane >> 4) & 1)*8)*PITCH_B
                               + ((lane >> 3) & 1)*16);
    for (int it = 0; it < NK; it++) {
        uint32_t aAddr = aBase + (uint32_t)((it & 1)*32*PITCH_A) + aOff;
        uint32_t bAddr = sb + bOff + (uint32_t)(it*128);
#pragma unroll
        for (int s16 = 0; s16 < 4; s16++) {
            uint32_t Ah[2][4], Bh[2][4];
#pragma unroll
            for (int mt = 0; mt < 2; mt++)
                ldm4(Ah[mt], aAddr + mt*16*PITCH_A + s16*32);
#pragma unroll
            for (int np = 0; np < 2; np++)
                ldm4(Bh[np], bAddr + np*16*PITCH_B + s16*32);
#pragma unroll
            for (int mt = 0; mt < 2; mt++)
#pragma unroll
            for (int nt = 0; nt < 4; nt++)
                mma_f16(acc[mt][nt], Ah[mt], &Bh[nt >> 1][(nt & 1)*2]);
        }
        // stage A(it+1) into other buffer; prefetch A(it+2)
        if (it + 1 < NK) {
            conv_storeA<BN>(aBasePtr + ((it + 1) & 1)*32*PITCH_A, ax,
                            (it + 1)*64 + qA*16, rsA, qA);
            if (it + 2 < NK) {
                const AT* ap = A + (size_t)((it + 2)*64 + qA*16)*ldn + nrow;
#pragma unroll
                for (int j = 0; j < 16; j++) ax[j] = (float)ap[(size_t)j*ldn];
            }
        }
        GBAR(1 + g);   // group-scoped: A(it+1) stored, stage (it)&1 free
    }
    __syncthreads();   // all groups done before epilogue overlays A region
}

// dump one 32-o strip into sbuf[o_local][n]  (n = 128, stride 132)
__device__ __forceinline__ void dump_strip(float* sbuf, int s, float acc[2][4][4]) {
    int t = threadIdx.x, lane = t & 31, wid = t >> 5;
    int g = wid >> 2, w = wid & 3;
    if (w != s) return;
    int gr = lane >> 2, c2 = (lane & 3)*2;
#pragma unroll
    for (int mt = 0; mt < 2; mt++)
#pragma unroll
    for (int nt = 0; nt < 4; nt++) {
        int nl = g*32 + mt*16 + gr;
        int ol = nt*8 + c2;
        sbuf[ol*132 + nl]         = acc[mt][nt][0];
        sbuf[(ol+1)*132 + nl]     = acc[mt][nt][1];
        sbuf[ol*132 + nl + 8]     = acc[mt][nt][2];
        sbuf[(ol+1)*132 + nl + 8] = acc[mt][nt][3];
    }
}

// ---------- Fused kernel: blocks 0..127 = kNN; 128..383 = GEMM 1a ----------
// GEMM 1a: Gt[b][n][o] = W1[:, :512] @ feat, fp16 out.
__global__ __launch_bounds__(512, 1)
void fused1a_kernel(const float* __restrict__ feat,
                    const float* __restrict__ xyz,
                    const float* __restrict__ xyzp) {
    extern __shared__ __align__(16) char sm[];
    if (blockIdx.x < 128) { knn_body(sm, xyz, xyzp, blockIdx.x); return; }
    constexpr int BSIZE = 128*(2*CPf + 16);
    uint32_t sb = smem_u32(sm);
    int gb = blockIdx.x - 128;
    int b = gb >> 5, nb = (gb & 15)*128, ob = ((gb >> 4) & 1)*128;
    int t = threadIdx.x;
    float acc[2][4][4] = {};
    gemm_core<CPf, false, float>(sm, sb, feat + (size_t)b*CPf*NP, NP, nb,
                                 g_W1_h, KW, ob, 0, acc);
    float* sbuf = (float*)(sm + BSIZE + O_SBUF);
    int n = t & 127, oq = t >> 7;
    for (int s = 0; s < 4; s++) {
        __syncthreads();
        dump_strip(sbuf, s, acc);
        __syncthreads();
        float f[8];
#pragma unroll
        for (int j = 0; j < 8; j++) f[j] = sbuf[(oq*8 + j)*132 + n];
        __half* dst = &g_Gt[((size_t)b*NP + nb + n)*C1f + ob + s*32 + oq*8];
        *(uint4*)dst = make_uint4(pack_h2(f[0], f[1]), pack_h2(f[2], f[3]),
                                  pack_h2(f[4], f[5]), pack_h2(f[6], f[7]));
    }
}

// shared epilogue: optional gather (fp16 Gt), transpose writeout [o][n] (fp16), BN-stat partials
__device__ __forceinline__ void epi_write(char* epi, float acc[2][4][4],
                                          __half* __restrict__ Y, int nb, int ob,
                                          int b, bool gather) {
    int t = threadIdx.x;
    float* sbuf = (float*)(epi + O_SBUF);
    int*   sid  = (int*)(epi + O_SID);
    float* swt  = (float*)(epi + O_SWT);
    float* chs  = (float*)(epi + O_CHS);
    float* chq  = (float*)(epi + O_CHQ);
    if (gather) {
        for (int i = t; i < 384; i += 512) {
            size_t base = ((size_t)b*N0 + nb)*3 + i;
            sid[i] = g_idx[base]; swt[i] = g_wt[base];
        }
    }
    const __half* Gt = g_Gt + (size_t)b*NP*C1f;
    for (int s = 0; s < 4; s++) {
        __syncthreads();
        dump_strip(sbuf, s, acc);
        __syncthreads();
        if (gather) {
            int n = t & 127, oq = t >> 7;
            float v[8];
#pragma unroll
            for (int j = 0; j < 8; j++) v[j] = sbuf[(oq*8 + j)*132 + n];
#pragma unroll
            for (int k = 0; k < 3; k++) {
                int   id = sid[n*3 + k];
                float wk = swt[n*3 + k];
                const __half* gp = &Gt[(size_t)id*C1f + ob + s*32 + oq*8];
                uint4 gv = *(const uint4*)gp;
                __half2 h; float2 f2;
                *(uint32_t*)&h = gv.x; f2 = __half22float2(h);
                v[0] = fmaf(wk, f2.x, v[0]); v[1] = fmaf(wk, f2.y, v[1]);
                *(uint32_t*)&h = gv.y; f2 = __half22float2(h);
                v[2] = fmaf(wk, f2.x, v[2]); v[3] = fmaf(wk, f2.y, v[3]);
                *(uint32_t*)&h = gv.z; f2 = __half22float2(h);
                v[4] = fmaf(wk, f2.x, v[4]); v[5] = fmaf(wk, f2.y, v[5]);
                *(uint32_t*)&h = gv.w; f2 = __half22float2(h);
                v[6] = fmaf(wk, f2.x, v[6]); v[7] = fmaf(wk, f2.y, v[7]);
            }
#pragma unroll
            for (int j = 0; j < 8; j++) sbuf[(oq*8 + j)*132 + n] = v[j];
            __syncthreads();
        }
        {
            int ol = t >> 4, seg = t & 15, n = seg*8;
            const float* srow = &sbuf[ol*132 + n];
            float4 x0 = *(const float4*)srow;
            float4 x1 = *(const float4*)(srow + 4);
            float s1 = x0.x + x0.y + x0.z + x0.w + x1.x + x1.y + x1.z + x1.w;
            float s2 = 0.f;
            s2 = fmaf(x0.x, x0.x, s2); s2 = fmaf(x0.y, x0.y, s2);
            s2 = fmaf(x0.z, x0.z, s2); s2 = fmaf(x0.w, x0.w, s2);
            s2 = fmaf(x1.x, x1.x, s2); s2 = fmaf(x1.y, x1.y, s2);
            s2 = fmaf(x1.z, x1.z, s2); s2 = fmaf(x1.w, x1.w, s2);
            __half* dst = &Y[(size_t)(ob + s*32 + ol)*N0 + nb + n];
            *(uint4*)dst = make_uint4(pack_h2(x0.x, x0.y), pack_h2(x0.z, x0.w),
                                      pack_h2(x1.x, x1.y), pack_h2(x1.z, x1.w));
#pragma unroll
            for (int off = 8; off; off >>= 1) {
                s1 += __shfl_down_sync(0xffffffffu, s1, off, 16);
                s2 += __shfl_down_sync(0xffffffffu, s2, off, 16);
            }
            if (seg == 0) { chs[s*32 + ol] = s1; chq[s*32 + ol] = s2; }
        }
    }
    __syncthreads();
    if (t < 128) {
        int pidx = blockIdx.x + 64*blockIdx.z;
        g_p1[(size_t)(ob + t)*512 + pidx] = chs[t];
        g_p2[(size_t)(ob + t)*512 + pidx] = chq[t];
    }
}

// ---- GEMM 1b: y1 = W1[:, 512:] @ skip + interp(Gt); fused stats; fp16 out ----
__global__ __launch_bounds__(512, 1)
void gemm1b_kernel(const float* __restrict__ skip) {
    extern __shared__ __align__(16) char sm[];
    constexpr int BSIZE = 128*(2*CSf + 16);
    uint32_t sb = smem_u32(sm);
    int b = blockIdx.z, nb = blockIdx.x*128, ob = blockIdx.y*128;
    float acc[2][4][4] = {};
    gemm_core<CSf, false, float>(sm, sb, skip + (size_t)b*CSf*N0, N0, nb,
                                 g_W1_h, KW, ob, CPf, acc);
    epi_write(sm + BSIZE, acc, g_y1 + (size_t)b*C1f*N0, nb, ob, b, true);
}

// ---- GEMM 2: z = W2 @ lrelu(BN1(y1)); y1 fp16 in, BN on A-stage; fp16 out ----
__global__ __launch_bounds__(512, 1)
void gemm2_kernel() {
    extern __shared__ __align__(16) char sm[];
    constexpr int BSIZE = 128*(2*C1f + 16);
    uint32_t sb = smem_u32(sm);
    int b = blockIdx.z, nb = blockIdx.x*128, ob = blockIdx.y*128;
    float acc[2][4][4] = {};
    gemm_core<C1f, true, __half>(sm, sb, g_y1 + (size_t)b*C1f*N0, N0, nb,
                                 g_W2_h, C1f, ob, 0, acc);
    epi_write(sm + BSIZE, acc, g_z + (size_t)b*C2f*N0, nb, ob, b, false);
}

// ---------------- stats reduce ----------------
__global__ void stats_reduce(const float* __restrict__ gain,
                             const float* __restrict__ beta, int layer) {
    int o = blockIdx.x, t = threadIdx.x;
    const float* p1 = &g_p1[(size_t)o*512];
    const float* p2 = &g_p2[(size_t)o*512];
    float a = p1[t] + p1[t+128] + p1[t+256] + p1[t+384];
    float c = p2[t] + p2[t+128] + p2[t+256] + p2[t+384];
    __shared__ float r1[128], r2[128];
    r1[t] = a; r2[t] = c; __syncthreads();
    for (int h = 64; h > 0; h >>= 1) {
        if (t < h) { r1[t] += r1[t+h]; r2[t] += r2[t+h]; }
        __syncthreads();
    }
    if (t == 0) {
        const float invN = 1.0f/((float)BB*N0);
        float m   = r1[0]*invN;
        float var = r2[0]*invN - m*m;
        float sc  = gain[o] * (1.0f/sqrtf(var + 1e-3f));
        if (layer) { g_sc2[o] = sc; g_bi2[o] = beta[o] - m*sc; }
        else       { g_sc1[o] = sc; g_bi1[o] = beta[o] - m*sc; }
    }
}

// ---------------- output: lrelu(BN2(z)), fp16 z -> fp32 out ----------------
__global__ void out_kernel(float* __restrict__ out) {
    size_t i = (size_t)blockIdx.x*blockDim.x + threadIdx.x;   // 8-half groups
    const size_t total8 = (size_t)BB*C2f*N0/8;
    if (i >= total8) return;
    int ch = (int)((i >> 10) & (C2f - 1));                    // N0/8 = 1024 groups/row
    float sc = g_sc2[ch], bi = g_bi2[ch];
    uint4 hv = *((const uint4*)g_z + i);
    float f[8];
    {
        __half2 h;
        *(uint32_t*)&h = hv.x; f[0] = __low2float(h); f[1] = __high2float(h);
        *(uint32_t*)&h = hv.y; f[2] = __low2float(h); f[3] = __high2float(h);
        *(uint32_t*)&h = hv.z; f[4] = __low2float(h); f[5] = __high2float(h);
        *(uint32_t*)&h = hv.w; f[6] = __low2float(h); f[7] = __high2float(h);
    }
#pragma unroll
    for (int j = 0; j < 8; j++) {
        float v = fmaf(f[j], sc, bi);
        f[j] = (v >= 0.f) ? v : 0.01f*v;
    }
    float* dst = out + i*8;
    *(float4*)dst       = make_float4(f[0], f[1], f[2], f[3]);
    *(float4*)(dst + 4) = make_float4(f[4], f[5], f[6], f[7]);
}

// ---------------- launch ----------------
extern "C" void kernel_launch(void* const* d_in, const int* in_sizes, int n_in,
                              void* d_out, int out_size) {
    const float* xyz   = (const float*)d_in[0];
    const float* skip  = (const float*)d_in[1];
    const float* xyzp  = (const float*)d_in[2];
    const float* featp = (const float*)d_in[3];
    const float* W1    = (const float*)d_in[4];
    const float* g1    = (const float*)d_in[5];
    const float* b1    = (const float*)d_in[6];
    const float* W2    = (const float*)d_in[7];
    const float* g2    = (const float*)d_in[8];
    const float* b2    = (const float*)d_in[9];
    float* out = (float*)d_out;

    const int SM1A = 128*(2*CPf + 16) + EPI_BYTES;   // 169984
    const int SM1B = 128*(2*CSf + 16) + EPI_BYTES;   // 104448
    const int SM2  = 128*(2*C1f + 16) + EPI_BYTES;   // 104448

    static int s_attr = 0;
    if (!s_attr) {
        cudaFuncSetAttribute(fused1a_kernel, cudaFuncAttributeMaxDynamicSharedMemorySize, SM1A);
        cudaFuncSetAttribute(gemm1b_kernel,  cudaFuncAttributeMaxDynamicSharedMemorySize, SM1B);
        cudaFuncSetAttribute(gemm2_kernel,   cudaFuncAttributeMaxDynamicSharedMemorySize, SM2);
        s_attr = 1;
    }

    __half *w1_h, *w2_h;
    cudaGetSymbolAddress((void**)&w1_h, g_W1_h);
    cudaGetSymbolAddress((void**)&w2_h, g_W2_h);

    const size_t xyz_elems = (size_t)BB*3*N0;
    const size_t nf_elems  = (size_t)BB*C2f*N0;
    size_t off = 0;
    if ((size_t)out_size >= xyz_elems + nf_elems) {
        cudaMemcpyAsync(out, xyz, xyz_elems*sizeof(float), cudaMemcpyDeviceToDevice);
        off = xyz_elems;
    }

    wconv_kernel  <<<(C1f*KW/2 + 255)/256,  256>>>(W1, w1_h, C1f*KW/2);
    wconv_kernel  <<<(C2f*C1f/2 + 255)/256, 256>>>(W2, w2_h, C2f*C1f/2);
    fused1a_kernel<<<384, 512, SM1A>>>(featp, xyz, xyzp);
    gemm1b_kernel <<<dim3(N0/128, C1f/128, BB), 512, SM1B>>>(skip);
    stats_reduce  <<<C1f, 128>>>(g1, b1, 0);
    gemm2_kernel  <<<dim3(N0/128, C2f/128, BB), 512, SM2>>>();
    stats_reduce  <<<C2f, 128>>>(g2, b2, 1);
    out_kernel    <<<(unsigned)((nf_elems/8 + 255)/256), 256>>>(out + off);
}

// round 15
// speedup vs baseline: 1.3384x; 1.0419x over previous
#include <cuda_runtime.h>
#include <cuda_fp16.h>
#include <cstdint>

#define BB  8
#define N0  8192
#define NP  2048
#define CPf 512
#define CSf 256
#define C1f 256
#define C2f 256
#define KW  768   // CP+CS

#define PITCH_A 144              // 64 fp16 + 16B pad
#define EPI_BYTES 36864
// epilogue overlay offsets (relative to A-region base = B panel size)
#define O_SBUF 0                 // 32 x 132 floats = 16896
#define O_SID  16896             // 384 int
#define O_SWT  18432             // 384 float
#define O_CHS  19968             // 128 float
#define O_CHQ  20480             // 128 float

// gemm1b custom layout
#define B1B_PITCH 528            // 2*CSf + 16
#define B1B_SIZE  67584          // 128 * 528
#define A1B_OFF   67584          // A buffers: 36864
#define G_OFF     104448         // gather buffer: 384 rows x 272 B
#define G_ROW     272
#define T_OFF     208896         // tail: swt | sid | chs | chq
#define SM1B_SZ   212992

// ---------------- scratch (device globals) ----------------
__device__ int    g_idx[BB*N0*3];
__device__ float  g_wt [BB*N0*3];
__device__ __align__(16) __half g_Gt[BB*NP*C1f];   // fp16 interp source
__device__ __align__(16) __half g_y1[BB*C1f*N0];   // fp16 pre-BN layer-1 output
__device__ __align__(16) __half g_z [BB*C2f*N0];   // fp16 pre-BN layer-2 output
__device__ float  g_p1 [C1f*512], g_p2[C1f*512];
__device__ float  g_sc1[C1f], g_bi1[C1f], g_sc2[C2f], g_bi2[C2f];
__device__ __align__(16) __half g_W1_h[C1f*KW];
__device__ __align__(16) __half g_W2_h[C2f*C1f];

// ---------------- PTX wrappers ----------------
__device__ __forceinline__ uint32_t smem_u32(const void* p) {
    uint32_t a;
    asm("{ .reg .u64 t; cvta.to.shared.u64 t, %1; cvt.u32.u64 %0, t; }" : "=r"(a) : "l"(p));
    return a;
}
__device__ __forceinline__ void ldm4(uint32_t* r, uint32_t addr) {
    asm volatile("ldmatrix.sync.aligned.m8n8.x4.shared.b16 {%0,%1,%2,%3}, [%4];"
        : "=r"(r[0]), "=r"(r[1]), "=r"(r[2]), "=r"(r[3]) : "r"(addr));
}
__device__ __forceinline__ void mma_f16(float* d, const uint32_t* a, const uint32_t* b) {
    asm volatile("mma.sync.aligned.m16n8k16.row.col.f32.f16.f16.f32 "
        "{%0,%1,%2,%3}, {%4,%5,%6,%7}, {%8,%9}, {%0,%1,%2,%3};"
        : "+f"(d[0]), "+f"(d[1]), "+f"(d[2]), "+f"(d[3])
        : "r"(a[0]), "r"(a[1]), "r"(a[2]), "r"(a[3]), "r"(b[0]), "r"(b[1]));
}
__device__ __forceinline__ uint32_t pack_h2(float a, float b) {
    __half2 p = __floats2half2_rn(a, b);
    return *(uint32_t*)&p;
}
__device__ __forceinline__ void cpa16(uint32_t dst, const void* src) {
    asm volatile("cp.async.cg.shared.global [%0], [%1], 16;" :: "r"(dst), "l"(src) : "memory");
}
#define CP_COMMIT() asm volatile("cp.async.commit_group;" ::: "memory")
#define CP_WAIT(n)  asm volatile("cp.async.wait_group %0;" :: "n"(n) : "memory")
#define GBAR(id)    asm volatile("bar.sync %0, 128;" :: "r"(id) : "memory")

// ---------------- weight convert ----------------
__global__ void wconv_kernel(const float* __restrict__ w,
                             __half* __restrict__ hi, int npairs) {
    int i = blockIdx.x*blockDim.x + threadIdx.x;
    if (i >= npairs) return;
    ((uint32_t*)hi)[i] = pack_h2(w[2*i], w[2*i + 1]);
}

// ===================== kNN body (shifted-distance) =====================
__device__ __forceinline__ void knn_body(char* sm, const float* __restrict__ xyz,
                                         const float* __restrict__ xyzp, int kb) {
    float4* sp = (float4*)sm;
    int b = kb >> 4, nb = (kb & 15) << 9;
    int t = threadIdx.x;
    const float* p = xyzp + (size_t)b*3*NP;
    for (int j = t; j < NP; j += 512) {
        float X = p[j], Y = p[NP + j], Z = p[2*NP + j];
        sp[j] = make_float4(-2.f*X, -2.f*Y, -2.f*Z, X*X + Y*Y + Z*Z);
    }
    __syncthreads();
    int n = nb + t;
    const float* q = xyz + (size_t)b*3*N0;
    float qx = q[n], qy = q[N0 + n], qz = q[2*N0 + n];
    float q2 = qx*qx + qy*qy + qz*qz;
    float d0 = 1e30f, d1 = 1e30f, d2 = 1e30f;
    int   i0 = 0, i1 = 0, i2 = 0;
#pragma unroll 4
    for (int j = 0; j < NP; ++j) {
        float4 v = sp[j];
        float d = fmaf(qx, v.x, fmaf(qy, v.y, fmaf(qz, v.z, v.w)));
        if (d < d2) {
            if (d < d1) {
                d2 = d1; i2 = i1;
                if (d < d0) { d1 = d0; i1 = i0; d0 = d; i0 = j; }
                else        { d1 = d;  i1 = j; }
            } else { d2 = d; i2 = j; }
        }
    }
    float e0 = 1.0f/(fmaxf(d0 + q2, 1e-10f) + 1e-8f);
    float e1 = 1.0f/(fmaxf(d1 + q2, 1e-10f) + 1e-8f);
    float e2 = 1.0f/(fmaxf(d2 + q2, 1e-10f) + 1e-8f);
    float inv = 1.0f/(e0 + e1 + e2);
    size_t base = ((size_t)b*N0 + n)*3;
    g_idx[base]   = i0; g_idx[base+1] = i1; g_idx[base+2] = i2;
    g_wt [base]   = e0*inv; g_wt[base+1] = e1*inv; g_wt[base+2] = e2*inv;
}

// ===================== fp16 mma.sync GEMM core (shared by fused1a/gemm2) =====================
template<bool BN>
__device__ __forceinline__ void conv_storeA(char* dststage, const float* ax,
                                            int kA, int rsA, int qA) {
    float x[16];
#pragma unroll
    for (int j = 0; j < 16; j++) x[j] = ax[j];
    if (BN) {
#pragma unroll
        for (int j = 0; j < 16; j++) {
            float v = fmaf(x[j], g_sc1[kA + j], g_bi1[kA + j]);
            x[j] = (v >= 0.f) ? v : 0.01f*v;
        }
    }
    char* arow = dststage + rsA*PITCH_A + qA*32;
    *(uint4*)arow = make_uint4(pack_h2(x[0], x[1]),  pack_h2(x[2], x[3]),
                               pack_h2(x[4], x[5]),  pack_h2(x[6], x[7]));
    *(uint4*)(arow + 16) = make_uint4(pack_h2(x[8], x[9]),   pack_h2(x[10], x[11]),
                                      pack_h2(x[12], x[13]), pack_h2(x[14], x[15]));
}

template<int KFULL, bool BN, typename AT>
__device__ __forceinline__ void gemm_core(char* sm, uint32_t sb,
    const AT* __restrict__ A, int ldn, int nb,
    const __half* __restrict__ Wh, int ldw, int ob, int kW0,
    float acc[2][4][4])
{
    constexpr int PITCH_B = 2*KFULL + 16;
    constexpr int BSIZE   = 128*PITCH_B;
    constexpr int NK      = KFULL/64;
    constexpr int SEGS    = KFULL/8;
    int t = threadIdx.x, lane = t & 31, wid = t >> 5;
    int g = wid >> 2, w = wid & 3;
    int tg = t & 127, rsA = tg & 31, qA = tg >> 5;
    for (int i = t; i < 128*SEGS; i += 512) {
        int row = i/SEGS, seg = i%SEGS;
        cpa16(sb + row*PITCH_B + seg*16,
              Wh + (size_t)(ob + row)*ldw + kW0 + seg*8);
    }
    CP_COMMIT();
    char*    aBasePtr = sm + BSIZE + g*(2*32*PITCH_A);
    uint32_t aBase    = sb + (uint32_t)(BSIZE + g*(2*32*PITCH_A));
    int nrow = nb + g*32 + rsA;
    float ax[16];
    {
        const AT* ap = A + (size_t)(qA*16)*ldn + nrow;
#pragma unroll
        for (int j = 0; j < 16; j++) ax[j] = (float)ap[(size_t)j*ldn];
    }
    conv_storeA<BN>(aBasePtr, ax, qA*16, rsA, qA);
    if (NK > 1) {
        const AT* ap = A + (size_t)(64 + qA*16)*ldn + nrow;
#pragma unroll
        for (int j = 0; j < 16; j++) ax[j] = (float)ap[(size_t)j*ldn];
    }
    CP_WAIT(0);
    __syncthreads();
    uint32_t aOff = (uint32_t)((lane & 15)*PITCH_A + ((lane >> 4) & 1)*16);
    uint32_t bOff = (uint32_t)((w*32 + (lane & 7) + ((lane >> 4) & 1)*8)*PITCH_B
                               + ((lane >> 3) & 1)*16);
    for (int it = 0; it < NK; it++) {
        uint32_t aAddr = aBase + (uint32_t)((it & 1)*32*PITCH_A) + aOff;
        uint32_t bAddr = sb + bOff + (uint32_t)(it*128);
#pragma unroll
        for (int s16 = 0; s16 < 4; s16++) {
            uint32_t Ah[2][4], Bh[2][4];
#pragma unroll
            for (int mt = 0; mt < 2; mt++)
                ldm4(Ah[mt], aAddr + mt*16*PITCH_A + s16*32);
#pragma unroll
            for (int np = 0; np < 2; np++)
                ldm4(Bh[np], bAddr + np*16*PITCH_B + s16*32);
#pragma unroll
            for (int mt = 0; mt < 2; mt++)
#pragma unroll
            for (int nt = 0; nt < 4; nt++)
                mma_f16(acc[mt][nt], Ah[mt], &Bh[nt >> 1][(nt & 1)*2]);
        }
        if (it + 1 < NK) {
            conv_storeA<BN>(aBasePtr + ((it + 1) & 1)*32*PITCH_A, ax,
                            (it + 1)*64 + qA*16, rsA, qA);
            if (it + 2 < NK) {
                const AT* ap = A + (size_t)((it + 2)*64 + qA*16)*ldn + nrow;
#pragma unroll
                for (int j = 0; j < 16; j++) ax[j] = (float)ap[(size_t)j*ldn];
            }
        }
        GBAR(1 + g);
    }
    __syncthreads();
}

// dump one 32-o strip into sbuf[o_local][n]  (n = 128, stride 132)
__device__ __forceinline__ void dump_strip(float* sbuf, int s, float acc[2][4][4]) {
    int t = threadIdx.x, lane = t & 31, wid = t >> 5;
    int g = wid >> 2, w = wid & 3;
    if (w != s) return;
    int gr = lane >> 2, c2 = (lane & 3)*2;
#pragma unroll
    for (int mt = 0; mt < 2; mt++)
#pragma unroll
    for (int nt = 0; nt < 4; nt++) {
        int nl = g*32 + mt*16 + gr;
        int ol = nt*8 + c2;
        sbuf[ol*132 + nl]         = acc[mt][nt][0];
        sbuf[(ol+1)*132 + nl]     = acc[mt][nt][1];
        sbuf[ol*132 + nl + 8]     = acc[mt][nt][2];
        sbuf[(ol+1)*132 + nl + 8] = acc[mt][nt][3];
    }
}

// ---------- Fused kernel: blocks 0..127 = kNN; 128..383 = GEMM 1a (fp16 Gt out) ----------
__global__ __launch_bounds__(512, 1)
void fused1a_kernel(const float* __restrict__ feat,
                    const float* __restrict__ xyz,
                    const float* __restrict__ xyzp) {
    extern __shared__ __align__(16) char sm[];
    if (blockIdx.x < 128) { knn_body(sm, xyz, xyzp, blockIdx.x); return; }
    constexpr int BSIZE = 128*(2*CPf + 16);
    uint32_t sb = smem_u32(sm);
    int gb = blockIdx.x - 128;
    int b = gb >> 5, nb = (gb & 15)*128, ob = ((gb >> 4) & 1)*128;
    int t = threadIdx.x;
    float acc[2][4][4] = {};
    gemm_core<CPf, false, float>(sm, sb, feat + (size_t)b*CPf*NP, NP, nb,
                                 g_W1_h, KW, ob, 0, acc);
    float* sbuf = (float*)(sm + BSIZE + O_SBUF);
    int n = t & 127, oq = t >> 7;
    for (int s = 0; s < 4; s++) {
        __syncthreads();
        dump_strip(sbuf, s, acc);
        __syncthreads();
        float f[8];
#pragma unroll
        for (int j = 0; j < 8; j++) f[j] = sbuf[(oq*8 + j)*132 + n];
        __half* dst = &g_Gt[((size_t)b*NP + nb + n)*C1f + ob + s*32 + oq*8];
        *(uint4*)dst = make_uint4(pack_h2(f[0], f[1]), pack_h2(f[2], f[3]),
                                  pack_h2(f[4], f[5]), pack_h2(f[6], f[7]));
    }
}

// ---- GEMM 1b: y1 = W1[:, 512:] @ skip + interp(Gt); smem-staged gather; fp16 out ----
__global__ __launch_bounds__(512, 1)
void gemm1b_kernel(const float* __restrict__ skip) {
    extern __shared__ __align__(16) char sm[];
    constexpr int NK = CSf/64;      // 4
    uint32_t sb = smem_u32(sm);
    int b = blockIdx.z, nb = blockIdx.x*128, ob = blockIdx.y*128;
    int t = threadIdx.x, lane = t & 31, wid = t >> 5;
    int g = wid >> 2, w = wid & 3;
    int tg = t & 127, rsA = tg & 31, qA = tg >> 5;
    float* swt = (float*)(sm + T_OFF);
    int*   sid = (int*)(sm + T_OFF + 1536);
    float* chs = (float*)(sm + T_OFF + 3072);
    float* chq = (float*)(sm + T_OFF + 3584);
    // ---- group 0: B panel ----
    for (int i = t; i < 128*32; i += 512) {
        int row = i >> 5, seg = i & 31;
        cpa16(sb + row*B1B_PITCH + seg*16,
              g_W1_h + (size_t)(ob + row)*KW + CPf + seg*8);
    }
    CP_COMMIT();
    // ---- sid/swt, then group 1: gather rows into smem ----
    for (int i = t; i < 384; i += 512) {
        size_t base = ((size_t)b*N0 + nb)*3 + i;
        sid[i] = g_idx[base]; swt[i] = g_wt[base];
    }
    __syncthreads();
    {
        const __half* Gt = g_Gt + (size_t)b*NP*C1f + ob;
        for (int i = t; i < 384*16; i += 512) {
            int row = i >> 4, seg = i & 15;
            cpa16(sb + G_OFF + row*G_ROW + seg*16,
                  Gt + (size_t)sid[row]*C1f + seg*8);
        }
    }
    CP_COMMIT();
    // ---- A(0) + A(1) prefetch ----
    char*    aBasePtr = sm + A1B_OFF + g*(2*32*PITCH_A);
    uint32_t aBase    = sb + (uint32_t)(A1B_OFF + g*(2*32*PITCH_A));
    int nrow = nb + g*32 + rsA;
    const float* A = skip + (size_t)b*CSf*N0;
    float acc[2][4][4] = {};
    float ax[16];
    {
        const float* ap = A + (size_t)(qA*16)*N0 + nrow;
#pragma unroll
        for (int j = 0; j < 16; j++) ax[j] = ap[(size_t)j*N0];
    }
    conv_storeA<false>(aBasePtr, ax, qA*16, rsA, qA);
    {
        const float* ap = A + (size_t)(64 + qA*16)*N0 + nrow;
#pragma unroll
        for (int j = 0; j < 16; j++) ax[j] = ap[(size_t)j*N0];
    }
    CP_WAIT(1);     // B panel done; gather copies still in flight
    __syncthreads();
    uint32_t aOff = (uint32_t)((lane & 15)*PITCH_A + ((lane >> 4) & 1)*16);
    uint32_t bOff = (uint32_t)((w*32 + (lane & 7) + ((lane >> 4) & 1)*8)*B1B_PITCH
                               + ((lane >> 3) & 1)*16);
    for (int it = 0; it < NK; it++) {
        uint32_t aAddr = aBase + (uint32_t)((it & 1)*32*PITCH_A) + aOff;
        uint32_t bAddr = sb + bOff + (uint32_t)(it*128);
#pragma unroll
        for (int s16 = 0; s16 < 4; s16++) {
            uint32_t Ah[2][4], Bh[2][4];
#pragma unroll
            for (int mt = 0; mt < 2; mt++)
                ldm4(Ah[mt], aAddr + mt*16*PITCH_A + s16*32);
#pragma unroll
            for (int np = 0; np < 2; np++)
                ldm4(Bh[np], bAddr + np*16*B1B_PITCH + s16*32);
#pragma unroll
            for (int mt = 0; mt < 2; mt++)
#pragma unroll
            for (int nt = 0; nt < 4; nt++)
                mma_f16(acc[mt][nt], Ah[mt], &Bh[nt >> 1][(nt & 1)*2]);
        }
        if (it + 1 < NK) {
            conv_storeA<false>(aBasePtr + ((it + 1) & 1)*32*PITCH_A, ax,
                               (it + 1)*64 + qA*16, rsA, qA);
            if (it + 2 < NK) {
                const float* ap = A + (size_t)((it + 2)*64 + qA*16)*N0 + nrow;
#pragma unroll
                for (int j = 0; j < 16; j++) ax[j] = ap[(size_t)j*N0];
            }
        }
        GBAR(1 + g);
    }
    CP_WAIT(0);     // gather rows landed (long since)
    __syncthreads();
    // ---- epilogue: gather from smem, fp16 writeout, BN stats ----
    float* sbuf = (float*)sm;       // overlays B panel
    __half* Y = g_y1 + (size_t)b*C1f*N0;
    int n = t & 127, oq = t >> 7;
    for (int s = 0; s < 4; s++) {
        __syncthreads();
        dump_strip(sbuf, s, acc);
        __syncthreads();
        {
            float v[8];
#pragma unroll
            for (int j = 0; j < 8; j++) v[j] = sbuf[(oq*8 + j)*132 + n];
#pragma unroll
            for (int k = 0; k < 3; k++) {
                float wk = swt[n*3 + k];
                const char* gp = sm + G_OFF + (n*3 + k)*G_ROW + (s*32 + oq*8)*2;
                uint4 gv = *(const uint4*)gp;
                __half2 h; float2 f2;
                *(uint32_t*)&h = gv.x; f2 = __half22float2(h);
                v[0] = fmaf(wk, f2.x, v[0]); v[1] = fmaf(wk, f2.y, v[1]);
                *(uint32_t*)&h = gv.y; f2 = __half22float2(h);
                v[2] = fmaf(wk, f2.x, v[2]); v[3] = fmaf(wk, f2.y, v[3]);
                *(uint32_t*)&h = gv.z; f2 = __half22float2(h);
                v[4] = fmaf(wk, f2.x, v[4]); v[5] = fmaf(wk, f2.y, v[5]);
                *(uint32_t*)&h = gv.w; f2 = __half22float2(h);
                v[6] = fmaf(wk, f2.x, v[6]); v[7] = fmaf(wk, f2.y, v[7]);
            }
#pragma unroll
            for (int j = 0; j < 8; j++) sbuf[(oq*8 + j)*132 + n] = v[j];
        }
        __syncthreads();
        {
            int ol = t >> 4, seg = t & 15, nn = seg*8;
            const float* srow = &sbuf[ol*132 + nn];
            float4 x0 = *(const float4*)srow;
            float4 x1 = *(const float4*)(srow + 4);
            float s1 = x0.x + x0.y + x0.z + x0.w + x1.x + x1.y + x1.z + x1.w;
            float s2 = 0.f;
            s2 = fmaf(x0.x, x0.x, s2); s2 = fmaf(x0.y, x0.y, s2);
            s2 = fmaf(x0.z, x0.z, s2); s2 = fmaf(x0.w, x0.w, s2);
            s2 = fmaf(x1.x, x1.x, s2); s2 = fmaf(x1.y, x1.y, s2);
            s2 = fmaf(x1.z, x1.z, s2); s2 = fmaf(x1.w, x1.w, s2);
            __half* dst = &Y[(size_t)(ob + s*32 + ol)*N0 + nb + nn];
            *(uint4*)dst = make_uint4(pack_h2(x0.x, x0.y), pack_h2(x0.z, x0.w),
                                      pack_h2(x1.x, x1.y), pack_h2(x1.z, x1.w));
#pragma unroll
            for (int off = 8; off; off >>= 1) {
                s1 += __shfl_down_sync(0xffffffffu, s1, off, 16);
                s2 += __shfl_down_sync(0xffffffffu, s2, off, 16);
            }
            if (seg == 0) { chs[s*32 + ol] = s1; chq[s*32 + ol] = s2; }
        }
    }
    __syncthreads();
    if (t < 128) {
        int pidx = blockIdx.x + 64*blockIdx.z;
        g_p1[(size_t)(ob + t)*512 + pidx] = chs[t];
        g_p2[(size_t)(ob + t)*512 + pidx] = chq[t];
    }
}

// shared epilogue (no gather): transpose writeout [o][n] (fp16), BN-stat partials
__device__ __forceinline__ void epi_write(char* epi, float acc[2][4][4],
                                          __half* __restrict__ Y, int nb, int ob) {
    int t = threadIdx.x;
    float* sbuf = (float*)(epi + O_SBUF);
    float* chs  = (float*)(epi + O_CHS);
    float* chq  = (float*)(epi + O_CHQ);
    for (int s = 0; s < 4; s++) {
        __syncthreads();
        dump_strip(sbuf, s, acc);
        __syncthreads();
        {
            int ol = t >> 4, seg = t & 15, n = seg*8;
            const float* srow = &sbuf[ol*132 + n];
            float4 x0 = *(const float4*)srow;
            float4 x1 = *(const float4*)(srow + 4);
            float s1 = x0.x + x0.y + x0.z + x0.w + x1.x + x1.y + x1.z + x1.w;
            float s2 = 0.f;
            s2 = fmaf(x0.x, x0.x, s2); s2 = fmaf(x0.y, x0.y, s2);
            s2 = fmaf(x0.z, x0.z, s2); s2 = fmaf(x0.w, x0.w, s2);
            s2 = fmaf(x1.x, x1.x, s2); s2 = fmaf(x1.y, x1.y, s2);
            s2 = fmaf(x1.z, x1.z, s2); s2 = fmaf(x1.w, x1.w, s2);
            __half* dst = &Y[(size_t)(ob + s*32 + ol)*N0 + nb + n];
            *(uint4*)dst = make_uint4(pack_h2(x0.x, x0.y), pack_h2(x0.z, x0.w),
                                      pack_h2(x1.x, x1.y), pack_h2(x1.z, x1.w));
#pragma unroll
            for (int off = 8; off; off >>= 1) {
                s1 += __shfl_down_sync(0xffffffffu, s1, off, 16);
                s2 += __shfl_down_sync(0xffffffffu, s2, off, 16);
            }
            if (seg == 0) { chs[s*32 + ol] = s1; chq[s*32 + ol] = s2; }
        }
    }
    __syncthreads();
    if (t < 128) {
        int pidx = blockIdx.x + 64*blockIdx.z;
        g_p1[(size_t)(ob + t)*512 + pidx] = chs[t];
        g_p2[(size_t)(ob + t)*512 + pidx] = chq[t];
    }
}

// ---- GEMM 2: z = W2 @ lrelu(BN1(y1)); y1 fp16 in, BN on A-stage; fp16 out ----
__global__ __launch_bounds__(512, 1)
void gemm2_kernel() {
    extern __shared__ __align__(16) char sm[];
    constexpr int BSIZE = 128*(2*C1f + 16);
    uint32_t sb = smem_u32(sm);
    int b = blockIdx.z, nb = blockIdx.x*128, ob = blockIdx.y*128;
    float acc[2][4][4] = {};
    gemm_core<C1f, true, __half>(sm, sb, g_y1 + (size_t)b*C1f*N0, N0, nb,
                                 g_W2_h, C1f, ob, 0, acc);
    epi_write(sm + BSIZE, acc, g_z + (size_t)b*C2f*N0, nb, ob);
}

// ---------------- stats reduce ----------------
__global__ void stats_reduce(const float* __restrict__ gain,
                             const float* __restrict__ beta, int layer) {
    int o = blockIdx.x, t = threadIdx.x;
    const float* p1 = &g_p1[(size_t)o*512];
    const float* p2 = &g_p2[(size_t)o*512];
    float a = p1[t] + p1[t+128] + p1[t+256] + p1[t+384];
    float c = p2[t] + p2[t+128] + p2[t+256] + p2[t+384];
    __shared__ float r1[128], r2[128];
    r1[t] = a; r2[t] = c; __syncthreads();
    for (int h = 64; h > 0; h >>= 1) {
        if (t < h) { r1[t] += r1[t+h]; r2[t] += r2[t+h]; }
        __syncthreads();
    }
    if (t == 0) {
        const float invN = 1.0f/((float)BB*N0);
        float m   = r1[0]*invN;
        float var = r2[0]*invN - m*m;
        float sc  = gain[o] * (1.0f/sqrtf(var + 1e-3f));
        if (layer) { g_sc2[o] = sc; g_bi2[o] = beta[o] - m*sc; }
        else       { g_sc1[o] = sc; g_bi1[o] = beta[o] - m*sc; }
    }
}

// ---------------- output: lrelu(BN2(z)), fp16 z -> fp32 out ----------------
__global__ void out_kernel(float* __restrict__ out) {
    size_t i = (size_t)blockIdx.x*blockDim.x + threadIdx.x;
    const size_t total8 = (size_t)BB*C2f*N0/8;
    if (i >= total8) return;
    int ch = (int)((i >> 10) & (C2f - 1));
    float sc = g_sc2[ch], bi = g_bi2[ch];
    uint4 hv = *((const uint4*)g_z + i);
    float f[8];
    {
        __half2 h;
        *(uint32_t*)&h = hv.x; f[0] = __low2float(h); f[1] = __high2float(h);
        *(uint32_t*)&h = hv.y; f[2] = __low2float(h); f[3] = __high2float(h);
        *(uint32_t*)&h = hv.z; f[4] = __low2float(h); f[5] = __high2float(h);
        *(uint32_t*)&h = hv.w; f[6] = __low2float(h); f[7] = __high2float(h);
    }
#pragma unroll
    for (int j = 0; j < 8; j++) {
        float v = fmaf(f[j], sc, bi);
        f[j] = (v >= 0.f) ? v : 0.01f*v;
    }
    float* dst = out + i*8;
    *(float4*)dst       = make_float4(f[0], f[1], f[2], f[3]);
    *(float4*)(dst + 4) = make_float4(f[4], f[5], f[6], f[7]);
}

// ---------------- launch ----------------
extern "C" void kernel_launch(void* const* d_in, const int* in_sizes, int n_in,
                              void* d_out, int out_size) {
    const float* xyz   = (const float*)d_in[0];
    const float* skip  = (const float*)d_in[1];
    const float* xyzp  = (const float*)d_in[2];
    const float* featp = (const float*)d_in[3];
    const float* W1    = (const float*)d_in[4];
    const float* g1    = (const float*)d_in[5];
    const float* b1    = (const float*)d_in[6];
    const float* W2    = (const float*)d_in[7];
    const float* g2    = (const float*)d_in[8];
    const float* b2    = (const float*)d_in[9];
    float* out = (float*)d_out;

    const int SM1A = 128*(2*CPf + 16) + EPI_BYTES;   // 169984
    const int SM2  = 128*(2*C1f + 16) + EPI_BYTES;   // 104448

    static int s_attr = 0;
    if (!s_attr) {
        cudaFuncSetAttribute(fused1a_kernel, cudaFuncAttributeMaxDynamicSharedMemorySize, SM1A);
        cudaFuncSetAttribute(gemm1b_kernel,  cudaFuncAttributeMaxDynamicSharedMemorySize, SM1B_SZ);
        cudaFuncSetAttribute(gemm2_kernel,   cudaFuncAttributeMaxDynamicSharedMemorySize, SM2);
        s_attr = 1;
    }

    __half *w1_h, *w2_h;
    cudaGetSymbolAddress((void**)&w1_h, g_W1_h);
    cudaGetSymbolAddress((void**)&w2_h, g_W2_h);

    const size_t xyz_elems = (size_t)BB*3*N0;
    const size_t nf_elems  = (size_t)BB*C2f*N0;
    size_t off = 0;
    if ((size_t)out_size >= xyz_elems + nf_elems) {
        cudaMemcpyAsync(out, xyz, xyz_elems*sizeof(float), cudaMemcpyDeviceToDevice);
        off = xyz_elems;
    }

    wconv_kernel  <<<(C1f*KW/2 + 255)/256,  256>>>(W1, w1_h, C1f*KW/2);
    wconv_kernel  <<<(C2f*C1f/2 + 255)/256, 256>>>(W2, w2_h, C2f*C1f/2);
    fused1a_kernel<<<384, 512, SM1A>>>(featp, xyz, xyzp);
    gemm1b_kernel <<<dim3(N0/128, C1f/128, BB), 512, SM1B_SZ>>>(skip);
    stats_reduce  <<<C1f, 128>>>(g1, b1, 0);
    gemm2_kernel  <<<dim3(N0/128, C2f/128, BB), 512, SM2>>>();
    stats_reduce  <<<C2f, 128>>>(g2, b2, 1);
    out_kernel    <<<(unsigned)((nf_elems/8 + 255)/256), 256>>>(out + off);
}

// round 16
// speedup vs baseline: 1.3749x; 1.0273x over previous
#include <cuda_runtime.h>
#include <cuda_fp16.h>
#include <cstdint>

#define BB  8
#define N0  8192
#define NP  2048
#define CPf 512
#define CSf 256
#define C1f 256
#define C2f 256
#define KW  768   // CP+CS

#define PITCH_A 144              // 64 fp16 + 16B pad
#define EPI_BYTES 36864
// epilogue overlay offsets (relative to A-region base = B panel size)
#define O_SBUF 0                 // 32 x 132 floats = 16896
#define O_CHS  19968             // 128 float
#define O_CHQ  20480             // 128 float

// gemm1b / gemm2 shared-K layout (KFULL = 256)
#define B256_PITCH 528           // 2*256 + 16
#define B256_SIZE  67584         // 128 * 528
#define A256_OFF   67584         // A buffers: 4 groups x 2 x 32 x PITCH_A = 36864
#define G_OFF      104448        // gather buffer: 384 rows x 272 B
#define G_ROW      272
#define T_OFF      208896        // tail: swt(1536) | sid(1536) | chs(512) | chq(512)
#define SM1B_SZ    212992

// ---------------- scratch (device globals) ----------------
__device__ int    g_idx[BB*N0*3];
__device__ float  g_wt [BB*N0*3];
__device__ __align__(16) __half g_Gt[BB*NP*C1f];   // fp16 interp source [n][o]
__device__ __align__(16) __half g_y1[BB*N0*C1f];   // fp16 pre-BN y1, [n][c] layout!
__device__ __align__(16) __half g_z [BB*C2f*N0];   // fp16 pre-BN z, [c][n]
__device__ float  g_p1 [C1f*512], g_p2[C1f*512];
__device__ float  g_sc1[C1f], g_bi1[C1f], g_sc2[C2f], g_bi2[C2f];
__device__ __align__(16) __half g_W1_h[C1f*KW];
__device__ __align__(16) __half g_W2_h[C2f*C1f];

// ---------------- PTX wrappers ----------------
__device__ __forceinline__ uint32_t smem_u32(const void* p) {
    uint32_t a;
    asm("{ .reg .u64 t; cvta.to.shared.u64 t, %1; cvt.u32.u64 %0, t; }" : "=r"(a) : "l"(p));
    return a;
}
__device__ __forceinline__ void ldm4(uint32_t* r, uint32_t addr) {
    asm volatile("ldmatrix.sync.aligned.m8n8.x4.shared.b16 {%0,%1,%2,%3}, [%4];"
        : "=r"(r[0]), "=r"(r[1]), "=r"(r[2]), "=r"(r[3]) : "r"(addr));
}
__device__ __forceinline__ void mma_f16(float* d, const uint32_t* a, const uint32_t* b) {
    asm volatile("mma.sync.aligned.m16n8k16.row.col.f32.f16.f16.f32 "
        "{%0,%1,%2,%3}, {%4,%5,%6,%7}, {%8,%9}, {%0,%1,%2,%3};"
        : "+f"(d[0]), "+f"(d[1]), "+f"(d[2]), "+f"(d[3])
        : "r"(a[0]), "r"(a[1]), "r"(a[2]), "r"(a[3]), "r"(b[0]), "r"(b[1]));
}
__device__ __forceinline__ uint32_t pack_h2(float a, float b) {
    __half2 p = __floats2half2_rn(a, b);
    return *(uint32_t*)&p;
}
__device__ __forceinline__ void cpa16(uint32_t dst, const void* src) {
    asm volatile("cp.async.cg.shared.global [%0], [%1], 16;" :: "r"(dst), "l"(src) : "memory");
}
#define CP_COMMIT() asm volatile("cp.async.commit_group;" ::: "memory")
#define CP_WAIT(n)  asm volatile("cp.async.wait_group %0;" :: "n"(n) : "memory")
#define GBAR(id)    asm volatile("bar.sync %0, 128;" :: "r"(id) : "memory")

// ---------------- weight convert ----------------
__global__ void wconv_kernel(const float* __restrict__ w,
                             __half* __restrict__ hi, int npairs) {
    int i = blockIdx.x*blockDim.x + threadIdx.x;
    if (i >= npairs) return;
    ((uint32_t*)hi)[i] = pack_h2(w[2*i], w[2*i + 1]);
}

// ===================== kNN body (shifted-distance) =====================
__device__ __forceinline__ void knn_body(char* sm, const float* __restrict__ xyz,
                                         const float* __restrict__ xyzp, int kb) {
    float4* sp = (float4*)sm;
    int b = kb >> 4, nb = (kb & 15) << 9;
    int t = threadIdx.x;
    const float* p = xyzp + (size_t)b*3*NP;
    for (int j = t; j < NP; j += 512) {
        float X = p[j], Y = p[NP + j], Z = p[2*NP + j];
        sp[j] = make_float4(-2.f*X, -2.f*Y, -2.f*Z, X*X + Y*Y + Z*Z);
    }
    __syncthreads();
    int n = nb + t;
    const float* q = xyz + (size_t)b*3*N0;
    float qx = q[n], qy = q[N0 + n], qz = q[2*N0 + n];
    float q2 = qx*qx + qy*qy + qz*qz;
    float d0 = 1e30f, d1 = 1e30f, d2 = 1e30f;
    int   i0 = 0, i1 = 0, i2 = 0;
#pragma unroll 4
    for (int j = 0; j < NP; ++j) {
        float4 v = sp[j];
        float d = fmaf(qx, v.x, fmaf(qy, v.y, fmaf(qz, v.z, v.w)));
        if (d < d2) {
            if (d < d1) {
                d2 = d1; i2 = i1;
                if (d < d0) { d1 = d0; i1 = i0; d0 = d; i0 = j; }
                else        { d1 = d;  i1 = j; }
            } else { d2 = d; i2 = j; }
        }
    }
    float e0 = 1.0f/(fmaxf(d0 + q2, 1e-10f) + 1e-8f);
    float e1 = 1.0f/(fmaxf(d1 + q2, 1e-10f) + 1e-8f);
    float e2 = 1.0f/(fmaxf(d2 + q2, 1e-10f) + 1e-8f);
    float inv = 1.0f/(e0 + e1 + e2);
    size_t base = ((size_t)b*N0 + n)*3;
    g_idx[base]   = i0; g_idx[base+1] = i1; g_idx[base+2] = i2;
    g_wt [base]   = e0*inv; g_wt[base+1] = e1*inv; g_wt[base+2] = e2*inv;
}

// ===================== fp16 mma.sync GEMM core (fused1a) =====================
__device__ __forceinline__ void conv_storeA(char* dststage, const float* ax,
                                            int rsA, int qA) {
    char* arow = dststage + rsA*PITCH_A + qA*32;
    *(uint4*)arow = make_uint4(pack_h2(ax[0], ax[1]),  pack_h2(ax[2], ax[3]),
                               pack_h2(ax[4], ax[5]),  pack_h2(ax[6], ax[7]));
    *(uint4*)(arow + 16) = make_uint4(pack_h2(ax[8], ax[9]),   pack_h2(ax[10], ax[11]),
                                      pack_h2(ax[12], ax[13]), pack_h2(ax[14], ax[15]));
}

template<int KFULL>
__device__ __forceinline__ void gemm_core(char* sm, uint32_t sb,
    const float* __restrict__ A, int ldn, int nb,
    const __half* __restrict__ Wh, int ldw, int ob, int kW0,
    float acc[2][4][4])
{
    constexpr int PITCH_B = 2*KFULL + 16;
    constexpr int BSIZE   = 128*PITCH_B;
    constexpr int NK      = KFULL/64;
    constexpr int SEGS    = KFULL/8;
    int t = threadIdx.x, lane = t & 31, wid = t >> 5;
    int g = wid >> 2, w = wid & 3;
    int tg = t & 127, rsA = tg & 31, qA = tg >> 5;
    for (int i = t; i < 128*SEGS; i += 512) {
        int row = i/SEGS, seg = i%SEGS;
        cpa16(sb + row*PITCH_B + seg*16,
              Wh + (size_t)(ob + row)*ldw + kW0 + seg*8);
    }
    CP_COMMIT();
    char*    aBasePtr = sm + BSIZE + g*(2*32*PITCH_A);
    uint32_t aBase    = sb + (uint32_t)(BSIZE + g*(2*32*PITCH_A));
    int nrow = nb + g*32 + rsA;
    float ax[16];
    {
        const float* ap = A + (size_t)(qA*16)*ldn + nrow;
#pragma unroll
        for (int j = 0; j < 16; j++) ax[j] = ap[(size_t)j*ldn];
    }
    conv_storeA(aBasePtr, ax, rsA, qA);
    if (NK > 1) {
        const float* ap = A + (size_t)(64 + qA*16)*ldn + nrow;
#pragma unroll
        for (int j = 0; j < 16; j++) ax[j] = ap[(size_t)j*ldn];
    }
    CP_WAIT(0);
    __syncthreads();
    uint32_t aOff = (uint32_t)((lane & 15)*PITCH_A + ((lane >> 4) & 1)*16);
    uint32_t bOff = (uint32_t)((w*32 + (lane & 7) + ((lane >> 4) & 1)*8)*PITCH_B
                               + ((lane >> 3) & 1)*16);
    for (int it = 0; it < NK; it++) {
        uint32_t aAddr = aBase + (uint32_t)((it & 1)*32*PITCH_A) + aOff;
        uint32_t bAddr = sb + bOff + (uint32_t)(it*128);
#pragma unroll
        for (int s16 = 0; s16 < 4; s16++) {
            uint32_t Ah[2][4], Bh[2][4];
#pragma unroll
            for (int mt = 0; mt < 2; mt++)
                ldm4(Ah[mt], aAddr + mt*16*PITCH_A + s16*32);
#pragma unroll
            for (int np = 0; np < 2; np++)
                ldm4(Bh[np], bAddr + np*16*PITCH_B + s16*32);
#pragma unroll
            for (int mt = 0; mt < 2; mt++)
#pragma unroll
            for (int nt = 0; nt < 4; nt++)
                mma_f16(acc[mt][nt], Ah[mt], &Bh[nt >> 1][(nt & 1)*2]);
        }
        if (it + 1 < NK) {
            conv_storeA(aBasePtr + ((it + 1) & 1)*32*PITCH_A, ax, rsA, qA);
            if (it + 2 < NK) {
                const float* ap = A + (size_t)((it + 2)*64 + qA*16)*ldn + nrow;
#pragma unroll
                for (int j = 0; j < 16; j++) ax[j] = ap[(size_t)j*ldn];
            }
        }
        GBAR(1 + g);
    }
    __syncthreads();
}

// dump one 32-o strip into sbuf[o_local][n]  (n = 128, stride 132)
__device__ __forceinline__ void dump_strip(float* sbuf, int s, float acc[2][4][4]) {
    int t = threadIdx.x, lane = t & 31, wid = t >> 5;
    int g = wid >> 2, w = wid & 3;
    if (w != s) return;
    int gr = lane >> 2, c2 = (lane & 3)*2;
#pragma unroll
    for (int mt = 0; mt < 2; mt++)
#pragma unroll
    for (int nt = 0; nt < 4; nt++) {
        int nl = g*32 + mt*16 + gr;
        int ol = nt*8 + c2;
        sbuf[ol*132 + nl]         = acc[mt][nt][0];
        sbuf[(ol+1)*132 + nl]     = acc[mt][nt][1];
        sbuf[ol*132 + nl + 8]     = acc[mt][nt][2];
        sbuf[(ol+1)*132 + nl + 8] = acc[mt][nt][3];
    }
}

// ---------- Fused kernel: blocks 0..127 = kNN; 128..383 = GEMM 1a (fp16 Gt out) ----------
__global__ __launch_bounds__(512, 1)
void fused1a_kernel(const float* __restrict__ feat,
                    const float* __restrict__ xyz,
                    const float* __restrict__ xyzp) {
    extern __shared__ __align__(16) char sm[];
    if (blockIdx.x < 128) { knn_body(sm, xyz, xyzp, blockIdx.x); return; }
    constexpr int BSIZE = 128*(2*CPf + 16);
    uint32_t sb = smem_u32(sm);
    int gb = blockIdx.x - 128;
    int b = gb >> 5, nb = (gb & 15)*128, ob = ((gb >> 4) & 1)*128;
    int t = threadIdx.x;
    float acc[2][4][4] = {};
    gemm_core<CPf>(sm, sb, feat + (size_t)b*CPf*NP, NP, nb,
                   g_W1_h, KW, ob, 0, acc);
    float* sbuf = (float*)(sm + BSIZE + O_SBUF);
    int n = t & 127, oq = t >> 7;
    for (int s = 0; s < 4; s++) {
        __syncthreads();
        dump_strip(sbuf, s, acc);
        __syncthreads();
        float f[8];
#pragma unroll
        for (int j = 0; j < 8; j++) f[j] = sbuf[(oq*8 + j)*132 + n];
        __half* dst = &g_Gt[((size_t)b*NP + nb + n)*C1f + ob + s*32 + oq*8];
        *(uint4*)dst = make_uint4(pack_h2(f[0], f[1]), pack_h2(f[2], f[3]),
                                  pack_h2(f[4], f[5]), pack_h2(f[6], f[7]));
    }
}

// ---- GEMM 1b: y1[n][c] = W1[:, 512:] @ skip + interp(Gt); register-direct epilogue ----
__global__ __launch_bounds__(512, 1)
void gemm1b_kernel(const float* __restrict__ skip) {
    extern __shared__ __align__(16) char sm[];
    constexpr int NK = CSf/64;      // 4
    uint32_t sb = smem_u32(sm);
    int b = blockIdx.z, nb = blockIdx.x*128, ob = blockIdx.y*128;
    int t = threadIdx.x, lane = t & 31, wid = t >> 5;
    int g = wid >> 2, w = wid & 3;
    int tg = t & 127, rsA = tg & 31, qA = tg >> 5;
    float* swt = (float*)(sm + T_OFF);
    int*   sid = (int*)(sm + T_OFF + 1536);
    float* chs = (float*)(sm + T_OFF + 3072);
    float* chq = (float*)(sm + T_OFF + 3584);
    // ---- group 0: B panel ----
    for (int i = t; i < 128*32; i += 512) {
        int row = i >> 5, seg = i & 31;
        cpa16(sb + row*B256_PITCH + seg*16,
              g_W1_h + (size_t)(ob + row)*KW + CPf + seg*8);
    }
    CP_COMMIT();
    // ---- sid/swt, then group 1: gather rows into smem ----
    for (int i = t; i < 384; i += 512) {
        size_t base = ((size_t)b*N0 + nb)*3 + i;
        sid[i] = g_idx[base]; swt[i] = g_wt[base];
    }
    if (t < 128) { chs[t] = 0.f; chq[t] = 0.f; }
    __syncthreads();
    {
        const __half* Gt = g_Gt + (size_t)b*NP*C1f + ob;
        for (int i = t; i < 384*16; i += 512) {
            int row = i >> 4, seg = i & 15;
            cpa16(sb + G_OFF + row*G_ROW + seg*16,
                  Gt + (size_t)sid[row]*C1f + seg*8);
        }
    }
    CP_COMMIT();
    // ---- A(0) + A(1) prefetch ----
    char*    aBasePtr = sm + A256_OFF + g*(2*32*PITCH_A);
    uint32_t aBase    = sb + (uint32_t)(A256_OFF + g*(2*32*PITCH_A));
    int nrow = nb + g*32 + rsA;
    const float* A = skip + (size_t)b*CSf*N0;
    float acc[2][4][4] = {};
    float ax[16];
    {
        const float* ap = A + (size_t)(qA*16)*N0 + nrow;
#pragma unroll
        for (int j = 0; j < 16; j++) ax[j] = ap[(size_t)j*N0];
    }
    conv_storeA(aBasePtr, ax, rsA, qA);
    {
        const float* ap = A + (size_t)(64 + qA*16)*N0 + nrow;
#pragma unroll
        for (int j = 0; j < 16; j++) ax[j] = ap[(size_t)j*N0];
    }
    CP_WAIT(1);     // B panel done; gather copies still in flight
    __syncthreads();
    uint32_t aOff = (uint32_t)((lane & 15)*PITCH_A + ((lane >> 4) & 1)*16);
    uint32_t bOff = (uint32_t)((w*32 + (lane & 7) + ((lane >> 4) & 1)*8)*B256_PITCH
                               + ((lane >> 3) & 1)*16);
    for (int it = 0; it < NK; it++) {
        uint32_t aAddr = aBase + (uint32_t)((it & 1)*32*PITCH_A) + aOff;
        uint32_t bAddr = sb + bOff + (uint32_t)(it*128);
#pragma unroll
        for (int s16 = 0; s16 < 4; s16++) {
            uint32_t Ah[2][4], Bh[2][4];
#pragma unroll
            for (int mt = 0; mt < 2; mt++)
                ldm4(Ah[mt], aAddr + mt*16*PITCH_A + s16*32);
#pragma unroll
            for (int np = 0; np < 2; np++)
                ldm4(Bh[np], bAddr + np*16*B256_PITCH + s16*32);
#pragma unroll
            for (int mt = 0; mt < 2; mt++)
#pragma unroll
            for (int nt = 0; nt < 4; nt++)
                mma_f16(acc[mt][nt], Ah[mt], &Bh[nt >> 1][(nt & 1)*2]);
        }
        if (it + 1 < NK) {
            conv_storeA(aBasePtr + ((it + 1) & 1)*32*PITCH_A, ax, rsA, qA);
            if (it + 2 < NK) {
                const float* ap = A + (size_t)((it + 2)*64 + qA*16)*N0 + nrow;
#pragma unroll
                for (int j = 0; j < 16; j++) ax[j] = ap[(size_t)j*N0];
            }
        }
        GBAR(1 + g);
    }
    CP_WAIT(0);     // gather rows landed
    __syncthreads();
    // ---- register-direct epilogue: gather-add, [n][c] fp16 store, stats ----
    int gr = lane >> 2, c2l = (lane & 3)*2;
    __half* Y = g_y1 + ((size_t)b*N0 + nb)*C1f + ob;
    float sums[8] = {}, sq[8] = {};
#pragma unroll
    for (int mt = 0; mt < 2; mt++)
#pragma unroll
    for (int hf = 0; hf < 2; hf++) {
        int n = g*32 + mt*16 + gr + hf*8;
        float v[8];
#pragma unroll
        for (int nt = 0; nt < 4; nt++) {
            v[2*nt]   = acc[mt][nt][hf*2];
            v[2*nt+1] = acc[mt][nt][hf*2+1];
        }
#pragma unroll
        for (int k = 0; k < 3; k++) {
            float wk = swt[n*3 + k];
            const char* gp = sm + G_OFF + (n*3 + k)*G_ROW + (w*32 + c2l)*2;
#pragma unroll
            for (int nt = 0; nt < 4; nt++) {
                __half2 h = *(const __half2*)(gp + nt*16);
                float2 f2 = __half22float2(h);
                v[2*nt]   = fmaf(wk, f2.x, v[2*nt]);
                v[2*nt+1] = fmaf(wk, f2.y, v[2*nt+1]);
            }
        }
        uint32_t* dst = (uint32_t*)(Y + (size_t)n*C1f + w*32 + c2l);
#pragma unroll
        for (int nt = 0; nt < 4; nt++) dst[nt*4] = pack_h2(v[2*nt], v[2*nt+1]);
#pragma unroll
        for (int j = 0; j < 8; j++) {
            sums[j] += v[j];
            sq[j] = fmaf(v[j], v[j], sq[j]);
        }
    }
#pragma unroll
    for (int j = 0; j < 8; j++) {
#pragma unroll
        for (int off = 16; off >= 4; off >>= 1) {
            sums[j] += __shfl_down_sync(0xffffffffu, sums[j], off);
            sq[j]   += __shfl_down_sync(0xffffffffu, sq[j],   off);
        }
    }
    if (lane < 4) {
#pragma unroll
        for (int nt = 0; nt < 4; nt++) {
            int col = w*32 + nt*8 + lane*2;
            atomicAdd(&chs[col],   sums[2*nt]);
            atomicAdd(&chs[col+1], sums[2*nt+1]);
            atomicAdd(&chq[col],   sq[2*nt]);
            atomicAdd(&chq[col+1], sq[2*nt+1]);
        }
    }
    __syncthreads();
    if (t < 128) {
        int pidx = blockIdx.x + 64*blockIdx.z;
        g_p1[(size_t)(ob + t)*512 + pidx] = chs[t];
        g_p2[(size_t)(ob + t)*512 + pidx] = chq[t];
    }
}

// shared epilogue (no gather): transpose writeout [o][n] (fp16), BN-stat partials
__device__ __forceinline__ void epi_write(char* epi, float acc[2][4][4],
                                          __half* __restrict__ Y, int nb, int ob) {
    int t = threadIdx.x;
    float* sbuf = (float*)(epi + O_SBUF);
    float* chs  = (float*)(epi + O_CHS);
    float* chq  = (float*)(epi + O_CHQ);
    for (int s = 0; s < 4; s++) {
        __syncthreads();
        dump_strip(sbuf, s, acc);
        __syncthreads();
        {
            int ol = t >> 4, seg = t & 15, n = seg*8;
            const float* srow = &sbuf[ol*132 + n];
            float4 x0 = *(const float4*)srow;
            float4 x1 = *(const float4*)(srow + 4);
            float s1 = x0.x + x0.y + x0.z + x0.w + x1.x + x1.y + x1.z + x1.w;
            float s2 = 0.f;
            s2 = fmaf(x0.x, x0.x, s2); s2 = fmaf(x0.y, x0.y, s2);
            s2 = fmaf(x0.z, x0.z, s2); s2 = fmaf(x0.w, x0.w, s2);
            s2 = fmaf(x1.x, x1.x, s2); s2 = fmaf(x1.y, x1.y, s2);
            s2 = fmaf(x1.z, x1.z, s2); s2 = fmaf(x1.w, x1.w, s2);
            __half* dst = &Y[(size_t)(ob + s*32 + ol)*N0 + nb + n];
            *(uint4*)dst = make_uint4(pack_h2(x0.x, x0.y), pack_h2(x0.z, x0.w),
                                      pack_h2(x1.x, x1.y), pack_h2(x1.z, x1.w));
#pragma unroll
            for (int off = 8; off; off >>= 1) {
                s1 += __shfl_down_sync(0xffffffffu, s1, off, 16);
                s2 += __shfl_down_sync(0xffffffffu, s2, off, 16);
            }
            if (seg == 0) { chs[s*32 + ol] = s1; chq[s*32 + ol] = s2; }
        }
    }
    __syncthreads();
    if (t < 128) {
        int pidx = blockIdx.x + 64*blockIdx.z;
        g_p1[(size_t)(ob + t)*512 + pidx] = chs[t];
        g_p2[(size_t)(ob + t)*512 + pidx] = chq[t];
    }
}

// ---- GEMM 2: z[c][n] = W2 @ lrelu(BN1(y1[n][c])); contiguous fp16 A loads ----
__device__ __forceinline__ void conv2_store(char* dststage, const uint4* raw,
                                            int kA, int row, int seg) {
    uint32_t wds[8] = {raw[0].x, raw[0].y, raw[0].z, raw[0].w,
                       raw[1].x, raw[1].y, raw[1].z, raw[1].w};
    float x[16];
#pragma unroll
    for (int p = 0; p < 8; p++) {
        __half2 h; *(uint32_t*)&h = wds[p];
        float2 f2 = __half22float2(h);
        x[2*p] = f2.x; x[2*p+1] = f2.y;
    }
#pragma unroll
    for (int j = 0; j < 16; j++) {
        float v = fmaf(x[j], g_sc1[kA + j], g_bi1[kA + j]);
        x[j] = (v >= 0.f) ? v : 0.01f*v;
    }
    char* arow = dststage + row*PITCH_A + seg*32;
    *(uint4*)arow = make_uint4(pack_h2(x[0], x[1]),  pack_h2(x[2], x[3]),
                               pack_h2(x[4], x[5]),  pack_h2(x[6], x[7]));
    *(uint4*)(arow + 16) = make_uint4(pack_h2(x[8], x[9]),   pack_h2(x[10], x[11]),
                                      pack_h2(x[12], x[13]), pack_h2(x[14], x[15]));
}

__global__ __launch_bounds__(512, 1)
void gemm2_kernel() {
    extern __shared__ __align__(16) char sm[];
    constexpr int NK = C1f/64;      // 4
    uint32_t sb = smem_u32(sm);
    int b = blockIdx.z, nb = blockIdx.x*128, ob = blockIdx.y*128;
    int t = threadIdx.x, lane = t & 31, wid = t >> 5;
    int g = wid >> 2, w = wid & 3;
    int tg = t & 127, row = tg >> 2, seg = tg & 3;
    // ---- B panel once ----
    for (int i = t; i < 128*32; i += 512) {
        int r = i >> 5, sg = i & 31;
        cpa16(sb + r*B256_PITCH + sg*16,
              g_W2_h + (size_t)(ob + r)*C1f + sg*8);
    }
    CP_COMMIT();
    const __half* A = g_y1 + ((size_t)b*N0 + nb)*C1f;
    char*    aBasePtr = sm + A256_OFF + g*(2*32*PITCH_A);
    uint32_t aBase    = sb + (uint32_t)(A256_OFF + g*(2*32*PITCH_A));
    const __half* myA = A + (size_t)(g*32 + row)*C1f + seg*16;
    float acc[2][4][4] = {};
    uint4 axr[2];
    axr[0] = *(const uint4*)myA;
    axr[1] = *(const uint4*)(myA + 8);
    conv2_store(aBasePtr, axr, seg*16, row, seg);
    {
        const __half* ap = myA + 64;
        axr[0] = *(const uint4*)ap;
        axr[1] = *(const uint4*)(ap + 8);
    }
    CP_WAIT(0);
    __syncthreads();
    uint32_t aOff = (uint32_t)((lane & 15)*PITCH_A + ((lane >> 4) & 1)*16);
    uint32_t bOff = (uint32_t)((w*32 + (lane & 7) + ((lane >> 4) & 1)*8)*B256_PITCH
                               + ((lane >> 3) & 1)*16);
    for (int it = 0; it < NK; it++) {
        uint32_t aAddr = aBase + (uint32_t)((it & 1)*32*PITCH_A) + aOff;
        uint32_t bAddr = sb + bOff + (uint32_t)(it*128);
#pragma unroll
        for (int s16 = 0; s16 < 4; s16++) {
            uint32_t Ah[2][4], Bh[2][4];
#pragma unroll
            for (int mt = 0; mt < 2; mt++)
                ldm4(Ah[mt], aAddr + mt*16*PITCH_A + s16*32);
#pragma unroll
            for (int np = 0; np < 2; np++)
                ldm4(Bh[np], bAddr + np*16*B256_PITCH + s16*32);
#pragma unroll
            for (int mt = 0; mt < 2; mt++)
#pragma unroll
            for (int nt = 0; nt < 4; nt++)
                mma_f16(acc[mt][nt], Ah[mt], &Bh[nt >> 1][(nt & 1)*2]);
        }
        if (it + 1 < NK) {
            conv2_store(aBasePtr + ((it + 1) & 1)*32*PITCH_A, axr,
                        (it + 1)*64 + seg*16, row, seg);
            if (it + 2 < NK) {
                const __half* ap = myA + (it + 2)*64;
                axr[0] = *(const uint4*)ap;
                axr[1] = *(const uint4*)(ap + 8);
            }
        }
        GBAR(1 + g);
    }
    __syncthreads();
    epi_write(sm + B256_SIZE, acc, g_z + (size_t)b*C2f*N0, nb, ob);
}

// ---------------- stats reduce ----------------
__global__ void stats_reduce(const float* __restrict__ gain,
                             const float* __restrict__ beta, int layer) {
    int o = blockIdx.x, t = threadIdx.x;
    const float* p1 = &g_p1[(size_t)o*512];
    const float* p2 = &g_p2[(size_t)o*512];
    float a = p1[t] + p1[t+128] + p1[t+256] + p1[t+384];
    float c = p2[t] + p2[t+128] + p2[t+256] + p2[t+384];
    __shared__ float r1[128], r2[128];
    r1[t] = a; r2[t] = c; __syncthreads();
    for (int h = 64; h > 0; h >>= 1) {
        if (t < h) { r1[t] += r1[t+h]; r2[t] += r2[t+h]; }
        __syncthreads();
    }
    if (t == 0) {
        const float invN = 1.0f/((float)BB*N0);
        float m   = r1[0]*invN;
        float var = r2[0]*invN - m*m;
        float sc  = gain[o] * (1.0f/sqrtf(var + 1e-3f));
        if (layer) { g_sc2[o] = sc; g_bi2[o] = beta[o] - m*sc; }
        else       { g_sc1[o] = sc; g_bi1[o] = beta[o] - m*sc; }
    }
}

// ---------------- output: lrelu(BN2(z)), fp16 z -> fp32 out ----------------
__global__ void out_kernel(float* __restrict__ out) {
    size_t i = (size_t)blockIdx.x*blockDim.x + threadIdx.x;
    const size_t total8 = (size_t)BB*C2f*N0/8;
    if (i >= total8) return;
    int ch = (int)((i >> 10) & (C2f - 1));
    float sc = g_sc2[ch], bi = g_bi2[ch];
    uint4 hv = *((const uint4*)g_z + i);
    float f[8];
    {
        __half2 h;
        *(uint32_t*)&h = hv.x; f[0] = __low2float(h); f[1] = __high2float(h);
        *(uint32_t*)&h = hv.y; f[2] = __low2float(h); f[3] = __high2float(h);
        *(uint32_t*)&h = hv.z; f[4] = __low2float(h); f[5] = __high2float(h);
        *(uint32_t*)&h = hv.w; f[6] = __low2float(h); f[7] = __high2float(h);
    }
#pragma unroll
    for (int j = 0; j < 8; j++) {
        float v = fmaf(f[j], sc, bi);
        f[j] = (v >= 0.f) ? v : 0.01f*v;
    }
    float* dst = out + i*8;
    *(float4*)dst       = make_float4(f[0], f[1], f[2], f[3]);
    *(float4*)(dst + 4) = make_float4(f[4], f[5], f[6], f[7]);
}

// ---------------- launch ----------------
extern "C" void kernel_launch(void* const* d_in, const int* in_sizes, int n_in,
                              void* d_out, int out_size) {
    const float* xyz   = (const float*)d_in[0];
    const float* skip  = (const float*)d_in[1];
    const float* xyzp  = (const float*)d_in[2];
    const float* featp = (const float*)d_in[3];
    const float* W1    = (const float*)d_in[4];
    const float* g1    = (const float*)d_in[5];
    const float* b1    = (const float*)d_in[6];
    const float* W2    = (const float*)d_in[7];
    const float* g2    = (const float*)d_in[8];
    const float* b2    = (const float*)d_in[9];
    float* out = (float*)d_out;

    const int SM1A = 128*(2*CPf + 16) + EPI_BYTES;   // 169984
    const int SM2  = B256_SIZE + EPI_BYTES;          // 104448

    static int s_attr = 0;
    if (!s_attr) {
        cudaFuncSetAttribute(fused1a_kernel, cudaFuncAttributeMaxDynamicSharedMemorySize, SM1A);
        cudaFuncSetAttribute(gemm1b_kernel,  cudaFuncAttributeMaxDynamicSharedMemorySize, SM1B_SZ);
        cudaFuncSetAttribute(gemm2_kernel,   cudaFuncAttributeMaxDynamicSharedMemorySize, SM2);
        s_attr = 1;
    }

    __half *w1_h, *w2_h;
    cudaGetSymbolAddress((void**)&w1_h, g_W1_h);
    cudaGetSymbolAddress((void**)&w2_h, g_W2_h);

    const size_t xyz_elems = (size_t)BB*3*N0;
    const size_t nf_elems  = (size_t)BB*C2f*N0;
    size_t off = 0;
    if ((size_t)out_size >= xyz_elems + nf_elems) {
        cudaMemcpyAsync(out, xyz, xyz_elems*sizeof(float), cudaMemcpyDeviceToDevice);
        off = xyz_elems;
    }

    wconv_kernel  <<<(C1f*KW/2 + 255)/256,  256>>>(W1, w1_h, C1f*KW/2);
    wconv_kernel  <<<(C2f*C1f/2 + 255)/256, 256>>>(W2, w2_h, C2f*C1f/2);
    fused1a_kernel<<<384, 512, SM1A>>>(featp, xyz, xyzp);
    gemm1b_kernel <<<dim3(N0/128, C1f/128, BB), 512, SM1B_SZ>>>(skip);
    stats_reduce  <<<C1f, 128>>>(g1, b1, 0);
    gemm2_kernel  <<<dim3(N0/128, C2f/128, BB), 512, SM2>>>();
    stats_reduce  <<<C2f, 128>>>(g2, b2, 1);
    out_kernel    <<<(unsigned)((nf_elems/8 + 255)/256), 256>>>(out + off);
}